// round 5
// baseline (speedup 1.0000x reference)
#include <cuda_runtime.h>
#include <math.h>

// SpectralConv1d_plus: B=32, N=16384, C_in=C_out=32, MODES=512, conv width 5.
// Pruned DFT: only 512 of 8193 rfft bins are live, so a full FFT is wasted
// work. Factor N = 512*32; f = r + 32j (r<32, j<16), n = q + 512p.
//   forward:  A[r][q] = sum_p x[q+512p] e^{-2pi i r p/32}
//             B[r][q] = A[r][q] e^{-2pi i r q/N}
//             X[r+32j]= sum_q B[r][q] e^{-2pi i j q/512}
//   inverse (transpose): D[r][m] = e^{+2pi i r m/N} sum_j G[r+32j] e^{+2pi i j m/512}
//             y[m+512s] = sum_r Re( D[r][m] e^{+2pi i r s/32} )
// All fp32; rfft's 1/N, irfft's 1/N and the final *N fold into a single
// (f==0 ? 1 : 2)/N scale applied in k_conv (factor 2 = Hermitian mirror).

#define NFFT   16384
#define MODES  512
#define FCONV  508

// Scratch: __device__ globals (no allocation allowed).
__device__ float2 g_tw[NFFT];                   // e^{+2pi i k/N}
__device__ float  g_xt[32 * 32 * NFFT];         // [b][c][n]
__device__ float2 g_Xf[32 * MODES * 32];        // [b][f][i]
__device__ float2 g_Wt[MODES * 32 * 32];        // [f][i][o]
__device__ float2 g_Y1[32 * MODES * 32];        // [b][f][o]
__device__ float2 g_G [32 * 32 * MODES];        // [b][o][f]
__device__ float  g_yt[32 * 32 * NFFT];         // [b][o][n]

#define SMEM_FWD  ((16384 + 2 * 512 * 33 + 1024) * 4)        // 204800 B
#define SMEM_INV  ((2 * 512 * 33 + 1024 + 64) * 4)           // 139520 B
#define SMEM_CONV ((68 * 32 * 2 + 2 * 5120) * 4)             // 58368 B

// --------------------------------- init -----------------------------------
__global__ void k_init() {
    int k = blockIdx.x * blockDim.x + threadIdx.x;   // 64*256 = 16384
    float s, c;
    sincospif((float)k / 8192.0f, &s, &c);           // angle = 2*pi*k/N
    g_tw[k] = make_float2(c, s);
}

// x [B,N,C] -> g_xt [B,C,N]  (coalesced tile transpose)
__global__ void k_tin(const float* __restrict__ x) {
    __shared__ float t[32][33];
    int tx = threadIdx.x, ty = threadIdx.y;
    int n0 = blockIdx.x * 32, b = blockIdx.y;
#pragma unroll
    for (int k = 0; k < 4; k++) {
        int row = ty + k * 8;
        t[row][tx] = x[((size_t)b * NFFT + n0 + row) * 32 + tx];
    }
    __syncthreads();
#pragma unroll
    for (int k = 0; k < 4; k++) {
        int c = ty + k * 8;
        g_xt[((size_t)b * 32 + c) * NFFT + n0 + tx] = t[tx][c];
    }
}

// w_real/w_imag [i][o][f] -> g_Wt[f][i*32+o] float2
__global__ void k_wt(const float* __restrict__ wr, const float* __restrict__ wi) {
    __shared__ float tr[32][33], ti[32][33];
    int tx = threadIdx.x, ty = threadIdx.y;
    int f0 = blockIdx.x * 32, io0 = blockIdx.y * 32;
#pragma unroll
    for (int k = 0; k < 4; k++) {
        int row = ty + k * 8;
        tr[row][tx] = wr[(io0 + row) * MODES + f0 + tx];
        ti[row][tx] = wi[(io0 + row) * MODES + f0 + tx];
    }
    __syncthreads();
#pragma unroll
    for (int k = 0; k < 4; k++) {
        int fr = ty + k * 8;
        g_Wt[(f0 + fr) * 1024 + io0 + tx] = make_float2(tr[tx][fr], ti[tx][fr]);
    }
}

// ------------------------------ forward DFT --------------------------------
// One block per signal (b*32+i). 512 threads / 16 warps.
__global__ __launch_bounds__(512, 1) void k_fwd() {
    extern __shared__ float smem[];
    float*  xs    = smem;                        // 16384
    float*  Bre   = smem + 16384;                // 512*33
    float*  Bim   = Bre + 512 * 33;              // 512*33
    float2* w512v = (float2*)(Bim + 512 * 33);   // 512 float2

    int sig  = blockIdx.x;                       // b*32 + i
    int b    = sig >> 5, i = sig & 31;
    int tid  = threadIdx.x, lane = tid & 31, w = tid >> 5;

    const float4* xin = (const float4*)(g_xt + (size_t)sig * NFFT);
    for (int k = tid; k < NFFT / 4; k += 512) ((float4*)xs)[k] = xin[k];
    {   // e^{-2pi i t/512}
        float2 e = g_tw[(32 * tid) & (NFFT - 1)];
        w512v[tid] = make_float2(e.x, -e.y);
    }
    // per-lane 32-pt DFT row (r = lane): e^{-2pi i r p/32}
    float Wc[32], Ws[32];
#pragma unroll
    for (int p = 0; p < 32; p++) {
        float2 e = g_tw[((lane * p) & 31) * 512];
        Wc[p] = e.x; Ws[p] = -e.y;
    }
    __syncthreads();

    // stage A: warp w owns q in [w*32, w*32+32); lane = r
    int q0 = w * 32;
    for (int pass = 0; pass < 8; pass++) {
        int qq = q0 + pass * 4;
        float ar[4] = {0.f, 0.f, 0.f, 0.f}, ai[4] = {0.f, 0.f, 0.f, 0.f};
#pragma unroll
        for (int p = 0; p < 32; p++) {
            float4 xv = *(const float4*)(xs + qq + (p << 9));  // broadcast
            ar[0] += xv.x * Wc[p]; ai[0] += xv.x * Ws[p];
            ar[1] += xv.y * Wc[p]; ai[1] += xv.y * Ws[p];
            ar[2] += xv.z * Wc[p]; ai[2] += xv.z * Ws[p];
            ar[3] += xv.w * Wc[p]; ai[3] += xv.w * Ws[p];
        }
#pragma unroll
        for (int t = 0; t < 4; t++) {
            int q = qq + t;
            float2 e = g_tw[(lane * q) & (NFFT - 1)];   // e^{-2pi i r q/N}
            float ec = e.x, es = -e.y;
            Bre[q * 33 + lane] = ar[t] * ec - ai[t] * es;
            Bim[q * 33 + lane] = ar[t] * es + ai[t] * ec;
        }
    }
    __syncthreads();

    // stage B: warp w -> j in [4*(w&3), +4), q-partition (w>>2) of 128; lane = r
    int jbase = (w & 3) * 4, qp = w >> 2;
    float Xr[4] = {0.f, 0.f, 0.f, 0.f}, Xi[4] = {0.f, 0.f, 0.f, 0.f};
    for (int q = qp * 128; q < qp * 128 + 128; q++) {
        float br = Bre[q * 33 + lane], bi = Bim[q * 33 + lane];
#pragma unroll
        for (int jj = 0; jj < 4; jj++) {
            float2 wv = w512v[((jbase + jj) * q) & 511];  // broadcast
            Xr[jj] += br * wv.x - bi * wv.y;
            Xi[jj] += br * wv.y + bi * wv.x;
        }
    }
    __syncthreads();
    // cross-partition reduction (reuse xs region)
    float* pr = xs;            // [4][512]
    float* pi = xs + 2048;     // [4][512]
#pragma unroll
    for (int jj = 0; jj < 4; jj++) {
        int f = (jbase + jj) * 32 + lane;
        pr[qp * 512 + f] = Xr[jj];
        pi[qp * 512 + f] = Xi[jj];
    }
    __syncthreads();
    {
        int f = tid;
        float sr = pr[f] + pr[512 + f] + pr[1024 + f] + pr[1536 + f];
        float si = pi[f] + pi[512 + f] + pi[1024 + f] + pi[1536 + f];
        g_Xf[((size_t)b * MODES + f) * 32 + i] = make_float2(sr, si);
    }
}

// ------------------------------ channel mix --------------------------------
// Y1[b][f][o] = sum_i X[b][f][i] * W[i][o][f]; one block per f
__global__ void k_einsum() {
    __shared__ float2 Xs[1024];   // [b][i]
    __shared__ float2 Wsm[1024];  // [i][o]
    int f = blockIdx.x, tid = threadIdx.x;
    for (int k = tid; k < 1024; k += 256) {
        Wsm[k] = g_Wt[f * 1024 + k];
        int bb = k >> 5, ii = k & 31;
        Xs[k] = g_Xf[((size_t)bb * MODES + f) * 32 + ii];
    }
    __syncthreads();
    int o = tid & 31, bg = tid >> 5;
    for (int bb = bg; bb < 32; bb += 8) {
        float yr = 0.f, yi = 0.f;
#pragma unroll
        for (int ii = 0; ii < 32; ii++) {
            float2 xv = Xs[bb * 32 + ii];    // broadcast
            float2 wv = Wsm[ii * 32 + o];
            yr += xv.x * wv.x - xv.y * wv.y;
            yi += xv.x * wv.y + xv.y * wv.x;
        }
        g_Y1[((size_t)bb * MODES + f) * 32 + o] = make_float2(yr, yi);
    }
}

// ----------------------------- frequency conv ------------------------------
// G[b][o][f] = (f==0?1:2)/N * sum_{w5,c} Y1[b][f+w5][c] * k[w5][c][o]; f>=508 -> 0
__global__ void k_conv(const float* __restrict__ kre, const float* __restrict__ kim) {
    extern __shared__ float cs[];
    float2* Ys  = (float2*)cs;            // 68*32
    float*  krs = cs + 68 * 32 * 2;       // 5120
    float*  kis = krs + 5120;             // 5120
    int tx = threadIdx.x, ty = threadIdx.y;
    int tid = ty * 32 + tx;
    int b = blockIdx.y, f0 = blockIdx.x * 64;
    int nrows = min(68, 512 - f0);
    for (int k = tid; k < nrows * 32; k += 256)
        Ys[k] = g_Y1[((size_t)b * MODES + f0) * 32 + k];
    for (int k = tid; k < 5120; k += 256) { krs[k] = kre[k]; kis[k] = kim[k]; }
    __syncthreads();
    for (int c8 = 0; c8 < 8; c8++) {
        int fl = ty * 8 + c8;
        int f = f0 + fl;
        float gr = 0.f, gi = 0.f;
        if (f < FCONV) {
#pragma unroll
            for (int w5 = 0; w5 < 5; w5++)
#pragma unroll
                for (int c = 0; c < 32; c++) {
                    float2 yv = Ys[(fl + w5) * 32 + c];       // broadcast
                    gr += yv.x * krs[(w5 * 32 + c) * 32 + tx];
                    gi += yv.y * kis[(w5 * 32 + c) * 32 + tx];
                }
            float sc = (f == 0) ? (1.0f / NFFT) : (2.0f / NFFT);
            gr *= sc; gi *= sc;
        }
        g_G[((size_t)b * 32 + tx) * MODES + f] = make_float2(gr, gi);
    }
}

// ------------------------------ inverse DFT --------------------------------
// One block per signal (b*32+o). 512 threads.
__global__ __launch_bounds__(512, 1) void k_inv() {
    extern __shared__ float smem[];
    float*  Dre   = smem;                        // 512*33
    float*  Dim   = Dre + 512 * 33;              // 512*33
    float2* w512p = (float2*)(Dim + 512 * 33);   // 512 float2
    float2* cs32  = w512p + 512;                 // 32 float2

    int sig = blockIdx.x;
    int tid = threadIdx.x, lane = tid & 31, w = tid >> 5;

    w512p[tid] = g_tw[(32 * tid) & (NFFT - 1)];                 // e^{+2pi i t/512}
    if (tid < 32) cs32[tid] = g_tw[(512 * tid) & (NFFT - 1)];   // e^{+2pi i t/32}

    // per-lane column of G': r = lane, j < 16
    float Gr[16], Gi[16];
#pragma unroll
    for (int j = 0; j < 16; j++) {
        float2 g = g_G[(size_t)sig * MODES + lane + 32 * j];
        Gr[j] = g.x; Gi[j] = g.y;
    }
    __syncthreads();

    // stage 1: warp w owns m in [w*32, w*32+32); lane = r
    for (int mm = 0; mm < 32; mm++) {
        int m = w * 32 + mm;
        float dr = 0.f, di = 0.f;
#pragma unroll
        for (int j = 0; j < 16; j++) {
            float2 wv = w512p[(j * m) & 511];          // broadcast
            dr += Gr[j] * wv.x - Gi[j] * wv.y;
            di += Gr[j] * wv.y + Gi[j] * wv.x;
        }
        float2 e = g_tw[(lane * m) & (NFFT - 1)];      // e^{+2pi i r m/N}
        Dre[m * 33 + lane] = dr * e.x - di * e.y;
        Dim[m * 33 + lane] = dr * e.y + di * e.x;
    }
    __syncthreads();

    // stage 2: thread owns m = w*32+lane, produces all 32 s outputs
    int m = w * 32 + lane;
    float y[32];
#pragma unroll
    for (int s = 0; s < 32; s++) y[s] = 0.f;
    for (int r = 0; r < 32; r++) {
        float dr = Dre[m * 33 + r], di = Dim[m * 33 + r];  // conflict-free
#pragma unroll
        for (int s = 0; s < 32; s++) {
            float2 csv = cs32[(r * s) & 31];           // broadcast
            y[s] += dr * csv.x - di * csv.y;
        }
    }
    float* yo = g_yt + (size_t)sig * NFFT;
#pragma unroll
    for (int s = 0; s < 32; s++) yo[m + (s << 9)] = y[s];
}

// g_yt [B,C,N] -> out [B,N,C]
__global__ void k_tout(float* __restrict__ out) {
    __shared__ float t[32][33];
    int tx = threadIdx.x, ty = threadIdx.y;
    int n0 = blockIdx.x * 32, b = blockIdx.y;
#pragma unroll
    for (int k = 0; k < 4; k++) {
        int c = ty + k * 8;
        t[c][tx] = g_yt[((size_t)b * 32 + c) * NFFT + n0 + tx];
    }
    __syncthreads();
#pragma unroll
    for (int k = 0; k < 4; k++) {
        int row = ty + k * 8;
        out[((size_t)b * NFFT + n0 + row) * 32 + tx] = t[tx][row];
    }
}

extern "C" void kernel_launch(void* const* d_in, const int* in_sizes, int n_in,
                              void* d_out, int out_size) {
    const float* x  = (const float*)d_in[0];
    const float* wr = (const float*)d_in[1];
    const float* wi = (const float*)d_in[2];
    const float* kr = (const float*)d_in[3];
    const float* ki = (const float*)d_in[4];
    float* out = (float*)d_out;

    cudaFuncSetAttribute(k_fwd,  cudaFuncAttributeMaxDynamicSharedMemorySize, SMEM_FWD);
    cudaFuncSetAttribute(k_inv,  cudaFuncAttributeMaxDynamicSharedMemorySize, SMEM_INV);
    cudaFuncSetAttribute(k_conv, cudaFuncAttributeMaxDynamicSharedMemorySize, SMEM_CONV);

    k_init<<<64, 256>>>();
    k_tin<<<dim3(NFFT / 32, 32), dim3(32, 8)>>>(x);
    k_wt<<<dim3(16, 32), dim3(32, 8)>>>(wr, wi);
    k_fwd<<<1024, 512, SMEM_FWD>>>();
    k_einsum<<<512, 256>>>();
    k_conv<<<dim3(8, 32), dim3(32, 8), SMEM_CONV>>>(kr, ki);
    k_inv<<<1024, 512, SMEM_INV>>>();
    k_tout<<<dim3(NFFT / 32, 32), dim3(32, 8)>>>(out);
}

// round 6
// speedup vs baseline: 1.0344x; 1.0344x over previous
#include <cuda_runtime.h>
#include <math.h>

// SpectralConv1d_plus: B=32, N=16384, C_in=C_out=32, MODES=512, conv width 5.
// Pruned DFT (only 512 of 8193 bins live). N = 512*32; f = r + 32j, n = q + 512p.
//   forward:  A[r][q] = sum_p x[q+512p] e^{-2pi i r p/32}
//             B[r][q] = A[r][q] e^{-2pi i r q/N}        (register rotator)
//             X[r+32j]= sum_q B[r][q] e^{-2pi i j q/512} (fused, reg accumulators)
//   inverse:  D[r][m] = e^{+2pi i r m/N} sum_j G[r+32j] e^{+2pi i j m/512}
//             y[m+512s] = sum_r Re( D[r][m] e^{+2pi i r s/32} )
// All normalizations fold into (f==0 ? 1 : 2)/N applied in k_conv.

#define NFFT   16384
#define MODES  512
#define FCONV  508

__device__ float2 g_tw[NFFT];                   // e^{+2pi i k/N}
__device__ float  g_xt[32 * 32 * NFFT];         // [b][c][n]
__device__ float2 g_Xf[32 * MODES * 32];        // [b][f][i]
__device__ float2 g_Wt[MODES * 32 * 32];        // [f][i][o]
__device__ float2 g_Y1[32 * MODES * 32];        // [b][f][o]
__device__ float2 g_G [32 * 32 * MODES];        // [b][o][f]
__device__ float  g_yt[32 * 32 * NFFT];         // [b][o][n]

#define SMEM_FWD  ((2048 + 1024 + 16384) * 4)                 // 77824 B
#define SMEM_INV  ((8448 + 8448 + 1056 + 1024 + 64) * 4)      // 76160 B
#define SMEM_CONV ((68 * 32 * 2 + 2 * 5120) * 4)              // 58368 B

// --------------------------------- init -----------------------------------
__global__ void k_init() {
    int k = blockIdx.x * blockDim.x + threadIdx.x;   // 64*256 = 16384
    float s, c;
    sincospif((float)k / 8192.0f, &s, &c);           // angle = 2*pi*k/N
    g_tw[k] = make_float2(c, s);
}

// x [B,N,C] -> g_xt [B,C,N]
__global__ void k_tin(const float* __restrict__ x) {
    __shared__ float t[32][33];
    int tx = threadIdx.x, ty = threadIdx.y;
    int n0 = blockIdx.x * 32, b = blockIdx.y;
#pragma unroll
    for (int k = 0; k < 4; k++) {
        int row = ty + k * 8;
        t[row][tx] = x[((size_t)b * NFFT + n0 + row) * 32 + tx];
    }
    __syncthreads();
#pragma unroll
    for (int k = 0; k < 4; k++) {
        int c = ty + k * 8;
        g_xt[((size_t)b * 32 + c) * NFFT + n0 + tx] = t[tx][c];
    }
}

// w_real/w_imag [i][o][f] -> g_Wt[f][i*32+o] float2
__global__ void k_wt(const float* __restrict__ wr, const float* __restrict__ wi) {
    __shared__ float tr[32][33], ti[32][33];
    int tx = threadIdx.x, ty = threadIdx.y;
    int f0 = blockIdx.x * 32, io0 = blockIdx.y * 32;
#pragma unroll
    for (int k = 0; k < 4; k++) {
        int row = ty + k * 8;
        tr[row][tx] = wr[(io0 + row) * MODES + f0 + tx];
        ti[row][tx] = wi[(io0 + row) * MODES + f0 + tx];
    }
    __syncthreads();
#pragma unroll
    for (int k = 0; k < 4; k++) {
        int fr = ty + k * 8;
        g_Wt[(f0 + fr) * 1024 + io0 + tx] = make_float2(tr[tx][fr], ti[tx][fr]);
    }
}

// ------------------------------ forward DFT --------------------------------
// One block per signal (b*32+i). 512 threads / 16 warps, 2 CTAs/SM.
// Fused stage A+B: B[r][q] lives only in registers.
__global__ __launch_bounds__(512, 2) void k_fwd() {
    extern __shared__ float smem[];
    float2* Wtab = (float2*)smem;          // [p][r]: e^{-2pi i r p/32}   (8 KB)
    float2* w512 = Wtab + 1024;            // e^{-2pi i t/512}            (4 KB)
    float2* part = w512 + 512;             // [w][f] partials            (64 KB)

    int sig = blockIdx.x, b = sig >> 5, ci = sig & 31;
    int tid = threadIdx.x, lane = tid & 31, w = tid >> 5;

    {
        float2 e = g_tw[(tid << 5) & (NFFT - 1)];
        w512[tid] = make_float2(e.x, -e.y);
    }
    for (int k = tid; k < 1024; k += 512) {
        int p = k >> 5, r = k & 31;
        float2 e = g_tw[((r * p) & 31) << 9];
        Wtab[k] = make_float2(e.x, -e.y);
    }
    __syncthreads();

    const float* xg = g_xt + (size_t)sig * NFFT;

    float Xr[16], Xi[16];
#pragma unroll
    for (int j = 0; j < 16; j++) { Xr[j] = 0.f; Xi[j] = 0.f; }

    int q0 = w * 32;
    // rotator: e^{-2pi i lane q / N}, step e^{-2pi i lane / N}
    float2 e0 = g_tw[(lane * q0) & (NFFT - 1)];
    float tc = e0.x, ts = -e0.y;
    float2 ed = g_tw[lane];
    float dc = ed.x, ds = -ed.y;

    for (int g = 0; g < 8; g++) {
        int qq = q0 + g * 4;
        float ar[4] = {0.f,0.f,0.f,0.f}, ai[4] = {0.f,0.f,0.f,0.f};
#pragma unroll
        for (int p = 0; p < 32; p++) {
            float2 Wv = Wtab[(p << 5) + lane];                  // conflict-free LDS
            float4 xv = *(const float4*)(xg + qq + (p << 9));   // broadcast LDG
            ar[0] += xv.x * Wv.x; ai[0] += xv.x * Wv.y;
            ar[1] += xv.y * Wv.x; ai[1] += xv.y * Wv.y;
            ar[2] += xv.z * Wv.x; ai[2] += xv.z * Wv.y;
            ar[3] += xv.w * Wv.x; ai[3] += xv.w * Wv.y;
        }
        float br[4], bi[4];
#pragma unroll
        for (int t = 0; t < 4; t++) {
            br[t] = ar[t] * tc - ai[t] * ts;
            bi[t] = ar[t] * ts + ai[t] * tc;
            float ntc = tc * dc - ts * ds, nts = tc * ds + ts * dc;
            tc = ntc; ts = nts;
        }
#pragma unroll
        for (int j = 0; j < 16; j++) {
            int i0 = (j * qq) & 511;
            float2 w0 = w512[i0];
            float2 w1 = w512[(i0 + j) & 511];
            float2 w2 = w512[(i0 + 2 * j) & 511];
            float2 w3 = w512[(i0 + 3 * j) & 511];
            Xr[j] += br[0]*w0.x - bi[0]*w0.y;  Xi[j] += br[0]*w0.y + bi[0]*w0.x;
            Xr[j] += br[1]*w1.x - bi[1]*w1.y;  Xi[j] += br[1]*w1.y + bi[1]*w1.x;
            Xr[j] += br[2]*w2.x - bi[2]*w2.y;  Xi[j] += br[2]*w2.y + bi[2]*w2.x;
            Xr[j] += br[3]*w3.x - bi[3]*w3.y;  Xi[j] += br[3]*w3.y + bi[3]*w3.x;
        }
    }
#pragma unroll
    for (int j = 0; j < 16; j++)
        part[(w << 9) + (j << 5) + lane] = make_float2(Xr[j], Xi[j]);
    __syncthreads();
    {
        int f = tid;
        float sr = 0.f, si = 0.f;
#pragma unroll
        for (int ww = 0; ww < 16; ww++) {
            float2 v = part[(ww << 9) + f];
            sr += v.x; si += v.y;
        }
        g_Xf[((size_t)b * MODES + f) * 32 + ci] = make_float2(sr, si);
    }
}

// ------------------------------ channel mix --------------------------------
__global__ void k_einsum() {
    __shared__ float2 Xs[1024];   // [b][i]
    __shared__ float2 Wsm[1024];  // [i][o]
    int f = blockIdx.x, tid = threadIdx.x;
    for (int k = tid; k < 1024; k += 256) {
        Wsm[k] = g_Wt[f * 1024 + k];
        int bb = k >> 5, ii = k & 31;
        Xs[k] = g_Xf[((size_t)bb * MODES + f) * 32 + ii];
    }
    __syncthreads();
    int o = tid & 31, bg = tid >> 5;
    for (int bb = bg; bb < 32; bb += 8) {
        float yr = 0.f, yi = 0.f;
#pragma unroll
        for (int ii = 0; ii < 32; ii++) {
            float2 xv = Xs[bb * 32 + ii];
            float2 wv = Wsm[ii * 32 + o];
            yr += xv.x * wv.x - xv.y * wv.y;
            yi += xv.x * wv.y + xv.y * wv.x;
        }
        g_Y1[((size_t)bb * MODES + f) * 32 + o] = make_float2(yr, yi);
    }
}

// ----------------------------- frequency conv ------------------------------
__global__ void k_conv(const float* __restrict__ kre, const float* __restrict__ kim) {
    extern __shared__ float cs[];
    float2* Ys  = (float2*)cs;            // 68*32
    float*  krs = cs + 68 * 32 * 2;       // 5120
    float*  kis = krs + 5120;             // 5120
    int tx = threadIdx.x, ty = threadIdx.y;
    int tid = ty * 32 + tx;
    int b = blockIdx.y, f0 = blockIdx.x * 64;
    int nrows = min(68, 512 - f0);
    for (int k = tid; k < nrows * 32; k += 256)
        Ys[k] = g_Y1[((size_t)b * MODES + f0) * 32 + k];
    for (int k = tid; k < 5120; k += 256) { krs[k] = kre[k]; kis[k] = kim[k]; }
    __syncthreads();
    for (int c8 = 0; c8 < 8; c8++) {
        int fl = ty * 8 + c8;
        int f = f0 + fl;
        float gr = 0.f, gi = 0.f;
        if (f < FCONV) {
#pragma unroll
            for (int w5 = 0; w5 < 5; w5++)
#pragma unroll
                for (int c = 0; c < 32; c++) {
                    float2 yv = Ys[(fl + w5) * 32 + c];
                    gr += yv.x * krs[(w5 * 32 + c) * 32 + tx];
                    gi += yv.y * kis[(w5 * 32 + c) * 32 + tx];
                }
            float sc = (f == 0) ? (1.0f / NFFT) : (2.0f / NFFT);
            gr *= sc; gi *= sc;
        }
        g_G[((size_t)b * 32 + tx) * MODES + f] = make_float2(gr, gi);
    }
}

// ------------------------------ inverse DFT --------------------------------
// One block per signal. 512 threads, 2 CTAs/SM; D chunked 2 x 256 m.
__global__ __launch_bounds__(512, 2) void k_inv() {
    extern __shared__ float smem[];
    float*  Dre   = smem;                        // [256][33]
    float*  Dim   = Dre + 256 * 33;              // [256][33]
    float2* Gs    = (float2*)(Dim + 256 * 33);   // [j][33] padded (528 float2)
    float2* w512p = Gs + 528;                    // 512 float2: e^{+2pi i t/512}
    float2* cs32  = w512p + 512;                 // 32 float2:  e^{+2pi i t/32}

    int sig = blockIdx.x;
    int tid = threadIdx.x, lane = tid & 31, w = tid >> 5;

    w512p[tid] = g_tw[(tid << 5) & (NFFT - 1)];
    if (tid < 32) cs32[tid] = g_tw[tid << 9];
    {   // G -> smem [j][r] padded
        float2 gv = g_G[(size_t)sig * MODES + tid];
        Gs[(tid >> 5) * 33 + (tid & 31)] = gv;
    }
    __syncthreads();

    int s0   = (tid >> 8) << 4;   // 0 or 16
    int mloc = tid & 255;

    for (int c = 0; c < 2; c++) {
        int m0 = c << 8;
        // ---- stage 1: warp w owns m in [m0+w*16, +16); lane = r
        {
            int mbase = m0 + w * 16;
            float2 e0 = g_tw[(lane * mbase) & (NFFT - 1)];
            float tc = e0.x, ts = e0.y;
            float2 ed = g_tw[lane];
            float dc = ed.x, ds = ed.y;
            for (int mm = 0; mm < 16; mm++) {
                int m = mbase + mm;
                float dr = 0.f, di = 0.f;
#pragma unroll
                for (int j = 0; j < 16; j++) {
                    float2 gv = Gs[j * 33 + lane];       // invariant -> regs
                    float2 wv = w512p[(j * m) & 511];    // broadcast
                    dr += gv.x * wv.x - gv.y * wv.y;
                    di += gv.x * wv.y + gv.y * wv.x;
                }
                int ml = m - m0;
                Dre[ml * 33 + lane] = dr * tc - di * ts;
                Dim[ml * 33 + lane] = dr * ts + di * tc;
                float ntc = tc * dc - ts * ds, nts = tc * ds + ts * dc;
                tc = ntc; ts = nts;
            }
        }
        __syncthreads();
        // ---- stage 2: thread -> (mloc, s-half); lanes have consecutive mloc
        {
            float y[16];
#pragma unroll
            for (int k = 0; k < 16; k++) y[k] = 0.f;
#pragma unroll
            for (int r = 0; r < 32; r++) {
                float dr = Dre[mloc * 33 + r], di = Dim[mloc * 33 + r];
                int base = r * s0;
#pragma unroll
                for (int k = 0; k < 8; k++) {
                    float2 cv = cs32[(base + r * k) & 31];
                    float tpos = dr * cv.x - di * cv.y;
                    y[k] += tpos;
                    // s+8 term: multiply twiddle by i^r (compile-time folded)
                    if ((r & 3) == 0)      y[k + 8] += tpos;
                    else if ((r & 3) == 1) y[k + 8] -= dr * cv.y + di * cv.x;
                    else if ((r & 3) == 2) y[k + 8] -= tpos;
                    else                   y[k + 8] += dr * cv.y + di * cv.x;
                }
            }
            float* yo = g_yt + (size_t)sig * NFFT + (m0 + mloc);
#pragma unroll
            for (int k = 0; k < 16; k++)
                yo[(size_t)(s0 + k) << 9] = y[k];   // coalesced per s
        }
        __syncthreads();
    }
}

// g_yt [B,C,N] -> out [B,N,C]
__global__ void k_tout(float* __restrict__ out) {
    __shared__ float t[32][33];
    int tx = threadIdx.x, ty = threadIdx.y;
    int n0 = blockIdx.x * 32, b = blockIdx.y;
#pragma unroll
    for (int k = 0; k < 4; k++) {
        int c = ty + k * 8;
        t[c][tx] = g_yt[((size_t)b * 32 + c) * NFFT + n0 + tx];
    }
    __syncthreads();
#pragma unroll
    for (int k = 0; k < 4; k++) {
        int row = ty + k * 8;
        out[((size_t)b * NFFT + n0 + row) * 32 + tx] = t[tx][row];
    }
}

extern "C" void kernel_launch(void* const* d_in, const int* in_sizes, int n_in,
                              void* d_out, int out_size) {
    const float* x  = (const float*)d_in[0];
    const float* wr = (const float*)d_in[1];
    const float* wi = (const float*)d_in[2];
    const float* kr = (const float*)d_in[3];
    const float* ki = (const float*)d_in[4];
    float* out = (float*)d_out;

    cudaFuncSetAttribute(k_fwd,  cudaFuncAttributeMaxDynamicSharedMemorySize, SMEM_FWD);
    cudaFuncSetAttribute(k_inv,  cudaFuncAttributeMaxDynamicSharedMemorySize, SMEM_INV);
    cudaFuncSetAttribute(k_conv, cudaFuncAttributeMaxDynamicSharedMemorySize, SMEM_CONV);

    k_init<<<64, 256>>>();
    k_tin<<<dim3(NFFT / 32, 32), dim3(32, 8)>>>(x);
    k_wt<<<dim3(16, 32), dim3(32, 8)>>>(wr, wi);
    k_fwd<<<1024, 512, SMEM_FWD>>>();
    k_einsum<<<512, 256>>>();
    k_conv<<<dim3(8, 32), dim3(32, 8), SMEM_CONV>>>(kr, ki);
    k_inv<<<1024, 512, SMEM_INV>>>();
    k_tout<<<dim3(NFFT / 32, 32), dim3(32, 8)>>>(out);
}

// round 7
// speedup vs baseline: 1.2724x; 1.2301x over previous
#include <cuda_runtime.h>
#include <math.h>

// SpectralConv1d_plus: B=32, N=16384, C_in=C_out=32, MODES=512, conv width 5.
// Pruned DFT (only 512 of 8193 bins live). N = 512*32; f = r + 32j, n = q + 512p.
//   forward:  A[r][q] = sum_p x[q+512p] e^{-2pi i r p/32}
//             B[r][q] = A[r][q] e^{-2pi i r q/N}        (register rotator)
//             X[r+32j]= sum_q B[r][q] e^{-2pi i j q/512} (fused, reg accumulators)
//   inverse:  D[r][m] = e^{+2pi i r m/N} sum_j G[r+32j] e^{+2pi i j m/512}
//             y[m+512s] = sum_r Re( D[r][m] e^{+2pi i r s/32} )
// All normalizations fold into (f==0 ? 1 : 2)/N applied in k_conv.
// R6 lesson: __launch_bounds__(512,2) capped regs at 64 -> local-memory spills
// (HBM 1153 GB/s on k_fwd). This round: 1 CTA/SM, regs free, no spills.

#define NFFT   16384
#define MODES  512
#define FCONV  508

__device__ float2 g_tw[NFFT];                   // e^{+2pi i k/N}
__device__ float  g_xt[32 * 32 * NFFT];         // [b][c][n]
__device__ float2 g_Xf[32 * MODES * 32];        // [b][f][i]
__device__ float2 g_Wt[MODES * 32 * 32];        // [f][i][o]
__device__ float2 g_Y1[32 * MODES * 32];        // [b][f][o]
__device__ float2 g_G [32 * 32 * MODES];        // [b][o][f]
__device__ float  g_yt[32 * 32 * NFFT];         // [b][o][n]

#define SMEM_FWD  ((2048 + 1024 + 16384) * 4)                 // 77824 B
#define SMEM_INV  ((8448 + 8448 + 1056 + 1024 + 64) * 4)      // 76160 B
#define SMEM_CONV ((68 * 32 * 2 + 2 * 5120) * 4)              // 58368 B

// --------------------------------- init -----------------------------------
__global__ void k_init() {
    int k = blockIdx.x * blockDim.x + threadIdx.x;   // 64*256 = 16384
    float s, c;
    sincospif((float)k / 8192.0f, &s, &c);           // angle = 2*pi*k/N
    g_tw[k] = make_float2(c, s);
}

// x [B,N,C] -> g_xt [B,C,N]
__global__ void k_tin(const float* __restrict__ x) {
    __shared__ float t[32][33];
    int tx = threadIdx.x, ty = threadIdx.y;
    int n0 = blockIdx.x * 32, b = blockIdx.y;
#pragma unroll
    for (int k = 0; k < 4; k++) {
        int row = ty + k * 8;
        t[row][tx] = x[((size_t)b * NFFT + n0 + row) * 32 + tx];
    }
    __syncthreads();
#pragma unroll
    for (int k = 0; k < 4; k++) {
        int c = ty + k * 8;
        g_xt[((size_t)b * 32 + c) * NFFT + n0 + tx] = t[tx][c];
    }
}

// w_real/w_imag [i][o][f] -> g_Wt[f][i*32+o] float2
__global__ void k_wt(const float* __restrict__ wr, const float* __restrict__ wi) {
    __shared__ float tr[32][33], ti[32][33];
    int tx = threadIdx.x, ty = threadIdx.y;
    int f0 = blockIdx.x * 32, io0 = blockIdx.y * 32;
#pragma unroll
    for (int k = 0; k < 4; k++) {
        int row = ty + k * 8;
        tr[row][tx] = wr[(io0 + row) * MODES + f0 + tx];
        ti[row][tx] = wi[(io0 + row) * MODES + f0 + tx];
    }
    __syncthreads();
#pragma unroll
    for (int k = 0; k < 4; k++) {
        int fr = ty + k * 8;
        g_Wt[(f0 + fr) * 1024 + io0 + tx] = make_float2(tr[tx][fr], ti[tx][fr]);
    }
}

// ------------------------------ forward DFT --------------------------------
// One block per signal (b*32+i). 512 threads / 16 warps, 1 CTA/SM (regs free).
// Fused stage A+B: B[r][q] lives only in registers.
__global__ __launch_bounds__(512, 1) void k_fwd() {
    extern __shared__ float smem[];
    float2* Wtab = (float2*)smem;          // [p][r]: e^{-2pi i r p/32}   (8 KB)
    float2* w512 = Wtab + 1024;            // e^{-2pi i t/512}            (4 KB)
    float2* part = w512 + 512;             // [w][f] partials            (64 KB)

    int sig = blockIdx.x, b = sig >> 5, ci = sig & 31;
    int tid = threadIdx.x, lane = tid & 31, w = tid >> 5;

    {
        float2 e = g_tw[(tid << 5) & (NFFT - 1)];
        w512[tid] = make_float2(e.x, -e.y);
    }
    for (int k = tid; k < 1024; k += 512) {
        int p = k >> 5, r = k & 31;
        float2 e = g_tw[((r * p) & 31) << 9];
        Wtab[k] = make_float2(e.x, -e.y);
    }
    __syncthreads();

    const float* xg = g_xt + (size_t)sig * NFFT;

    float Xr[16], Xi[16];
#pragma unroll
    for (int j = 0; j < 16; j++) { Xr[j] = 0.f; Xi[j] = 0.f; }

    int q0 = w * 32;
    // rotator: e^{-2pi i lane q / N}, step e^{-2pi i lane / N}
    float2 e0 = g_tw[(lane * q0) & (NFFT - 1)];
    float tc = e0.x, ts = -e0.y;
    float2 ed = g_tw[lane];
    float dc = ed.x, ds = -ed.y;

    for (int g = 0; g < 8; g++) {
        int qq = q0 + g * 4;
        float ar[4] = {0.f,0.f,0.f,0.f}, ai[4] = {0.f,0.f,0.f,0.f};
#pragma unroll
        for (int p = 0; p < 32; p++) {
            float2 Wv = Wtab[(p << 5) + lane];                  // conflict-free LDS
            float4 xv = *(const float4*)(xg + qq + (p << 9));   // broadcast LDG
            ar[0] += xv.x * Wv.x; ai[0] += xv.x * Wv.y;
            ar[1] += xv.y * Wv.x; ai[1] += xv.y * Wv.y;
            ar[2] += xv.z * Wv.x; ai[2] += xv.z * Wv.y;
            ar[3] += xv.w * Wv.x; ai[3] += xv.w * Wv.y;
        }
        float br[4], bi[4];
#pragma unroll
        for (int t = 0; t < 4; t++) {
            br[t] = ar[t] * tc - ai[t] * ts;
            bi[t] = ar[t] * ts + ai[t] * tc;
            float ntc = tc * dc - ts * ds, nts = tc * ds + ts * dc;
            tc = ntc; ts = nts;
        }
#pragma unroll
        for (int j = 0; j < 16; j++) {
            int i0 = (j * qq) & 511;
            float2 w0 = w512[i0];
            float2 w1 = w512[(i0 + j) & 511];
            float2 w2 = w512[(i0 + 2 * j) & 511];
            float2 w3 = w512[(i0 + 3 * j) & 511];
            Xr[j] += br[0]*w0.x - bi[0]*w0.y;  Xi[j] += br[0]*w0.y + bi[0]*w0.x;
            Xr[j] += br[1]*w1.x - bi[1]*w1.y;  Xi[j] += br[1]*w1.y + bi[1]*w1.x;
            Xr[j] += br[2]*w2.x - bi[2]*w2.y;  Xi[j] += br[2]*w2.y + bi[2]*w2.x;
            Xr[j] += br[3]*w3.x - bi[3]*w3.y;  Xi[j] += br[3]*w3.y + bi[3]*w3.x;
        }
    }
#pragma unroll
    for (int j = 0; j < 16; j++)
        part[(w << 9) + (j << 5) + lane] = make_float2(Xr[j], Xi[j]);
    __syncthreads();
    {
        int f = tid;
        float sr = 0.f, si = 0.f;
#pragma unroll
        for (int ww = 0; ww < 16; ww++) {
            float2 v = part[(ww << 9) + f];
            sr += v.x; si += v.y;
        }
        g_Xf[((size_t)b * MODES + f) * 32 + ci] = make_float2(sr, si);
    }
}

// ------------------------------ channel mix --------------------------------
__global__ void k_einsum() {
    __shared__ float2 Xs[1024];   // [b][i]
    __shared__ float2 Wsm[1024];  // [i][o]
    int f = blockIdx.x, tid = threadIdx.x;
    for (int k = tid; k < 1024; k += 256) {
        Wsm[k] = g_Wt[f * 1024 + k];
        int bb = k >> 5, ii = k & 31;
        Xs[k] = g_Xf[((size_t)bb * MODES + f) * 32 + ii];
    }
    __syncthreads();
    int o = tid & 31, bg = tid >> 5;
    for (int bb = bg; bb < 32; bb += 8) {
        float yr = 0.f, yi = 0.f;
#pragma unroll
        for (int ii = 0; ii < 32; ii++) {
            float2 xv = Xs[bb * 32 + ii];
            float2 wv = Wsm[ii * 32 + o];
            yr += xv.x * wv.x - xv.y * wv.y;
            yi += xv.x * wv.y + xv.y * wv.x;
        }
        g_Y1[((size_t)bb * MODES + f) * 32 + o] = make_float2(yr, yi);
    }
}

// ----------------------------- frequency conv ------------------------------
__global__ void k_conv(const float* __restrict__ kre, const float* __restrict__ kim) {
    extern __shared__ float cs[];
    float2* Ys  = (float2*)cs;            // 68*32
    float*  krs = cs + 68 * 32 * 2;       // 5120
    float*  kis = krs + 5120;             // 5120
    int tx = threadIdx.x, ty = threadIdx.y;
    int tid = ty * 32 + tx;
    int b = blockIdx.y, f0 = blockIdx.x * 64;
    int nrows = min(68, 512 - f0);
    for (int k = tid; k < nrows * 32; k += 256)
        Ys[k] = g_Y1[((size_t)b * MODES + f0) * 32 + k];
    for (int k = tid; k < 5120; k += 256) { krs[k] = kre[k]; kis[k] = kim[k]; }
    __syncthreads();
    for (int c8 = 0; c8 < 8; c8++) {
        int fl = ty * 8 + c8;
        int f = f0 + fl;
        float gr = 0.f, gi = 0.f;
        if (f < FCONV) {
#pragma unroll
            for (int w5 = 0; w5 < 5; w5++)
#pragma unroll
                for (int c = 0; c < 32; c++) {
                    float2 yv = Ys[(fl + w5) * 32 + c];
                    gr += yv.x * krs[(w5 * 32 + c) * 32 + tx];
                    gi += yv.y * kis[(w5 * 32 + c) * 32 + tx];
                }
            float sc = (f == 0) ? (1.0f / NFFT) : (2.0f / NFFT);
            gr *= sc; gi *= sc;
        }
        g_G[((size_t)b * 32 + tx) * MODES + f] = make_float2(gr, gi);
    }
}

// ------------------------------ inverse DFT --------------------------------
// One block per signal. 512 threads, 1 CTA/SM (regs free); D chunked 2 x 256 m.
__global__ __launch_bounds__(512, 1) void k_inv() {
    extern __shared__ float smem[];
    float*  Dre   = smem;                        // [256][33]
    float*  Dim   = Dre + 256 * 33;              // [256][33]
    float2* Gs    = (float2*)(Dim + 256 * 33);   // [j][33] padded (528 float2)
    float2* w512p = Gs + 528;                    // 512 float2: e^{+2pi i t/512}
    float2* cs32  = w512p + 512;                 // 32 float2:  e^{+2pi i t/32}

    int sig = blockIdx.x;
    int tid = threadIdx.x, lane = tid & 31, w = tid >> 5;

    w512p[tid] = g_tw[(tid << 5) & (NFFT - 1)];
    if (tid < 32) cs32[tid] = g_tw[tid << 9];
    {   // G -> smem [j][r] padded
        float2 gv = g_G[(size_t)sig * MODES + tid];
        Gs[(tid >> 5) * 33 + (tid & 31)] = gv;
    }
    __syncthreads();

    int s0   = (tid >> 8) << 4;   // 0 or 16
    int mloc = tid & 255;

    for (int c = 0; c < 2; c++) {
        int m0 = c << 8;
        // ---- stage 1: warp w owns m in [m0+w*16, +16); lane = r
        {
            int mbase = m0 + w * 16;
            float2 e0 = g_tw[(lane * mbase) & (NFFT - 1)];
            float tc = e0.x, ts = e0.y;
            float2 ed = g_tw[lane];
            float dc = ed.x, ds = ed.y;
            for (int mm = 0; mm < 16; mm++) {
                int m = mbase + mm;
                float dr = 0.f, di = 0.f;
#pragma unroll
                for (int j = 0; j < 16; j++) {
                    float2 gv = Gs[j * 33 + lane];       // invariant -> regs
                    float2 wv = w512p[(j * m) & 511];    // broadcast
                    dr += gv.x * wv.x - gv.y * wv.y;
                    di += gv.x * wv.y + gv.y * wv.x;
                }
                int ml = m - m0;
                Dre[ml * 33 + lane] = dr * tc - di * ts;
                Dim[ml * 33 + lane] = dr * ts + di * tc;
                float ntc = tc * dc - ts * ds, nts = tc * ds + ts * dc;
                tc = ntc; ts = nts;
            }
        }
        __syncthreads();
        // ---- stage 2: thread -> (mloc, s-half); lanes have consecutive mloc
        {
            float y[16];
#pragma unroll
            for (int k = 0; k < 16; k++) y[k] = 0.f;
#pragma unroll
            for (int r = 0; r < 32; r++) {
                float dr = Dre[mloc * 33 + r], di = Dim[mloc * 33 + r];
                int base = r * s0;
#pragma unroll
                for (int k = 0; k < 8; k++) {
                    float2 cv = cs32[(base + r * k) & 31];
                    float tpos = dr * cv.x - di * cv.y;
                    y[k] += tpos;
                    // s+8 term: multiply twiddle by i^r (compile-time folded)
                    if ((r & 3) == 0)      y[k + 8] += tpos;
                    else if ((r & 3) == 1) y[k + 8] -= dr * cv.y + di * cv.x;
                    else if ((r & 3) == 2) y[k + 8] -= tpos;
                    else                   y[k + 8] += dr * cv.y + di * cv.x;
                }
            }
            float* yo = g_yt + (size_t)sig * NFFT + (m0 + mloc);
#pragma unroll
            for (int k = 0; k < 16; k++)
                yo[(size_t)(s0 + k) << 9] = y[k];   // coalesced per s
        }
        __syncthreads();
    }
}

// g_yt [B,C,N] -> out [B,N,C]
__global__ void k_tout(float* __restrict__ out) {
    __shared__ float t[32][33];
    int tx = threadIdx.x, ty = threadIdx.y;
    int n0 = blockIdx.x * 32, b = blockIdx.y;
#pragma unroll
    for (int k = 0; k < 4; k++) {
        int c = ty + k * 8;
        t[c][tx] = g_yt[((size_t)b * 32 + c) * NFFT + n0 + tx];
    }
    __syncthreads();
#pragma unroll
    for (int k = 0; k < 4; k++) {
        int row = ty + k * 8;
        out[((size_t)b * NFFT + n0 + row) * 32 + tx] = t[tx][row];
    }
}

extern "C" void kernel_launch(void* const* d_in, const int* in_sizes, int n_in,
                              void* d_out, int out_size) {
    const float* x  = (const float*)d_in[0];
    const float* wr = (const float*)d_in[1];
    const float* wi = (const float*)d_in[2];
    const float* kr = (const float*)d_in[3];
    const float* ki = (const float*)d_in[4];
    float* out = (float*)d_out;

    cudaFuncSetAttribute(k_fwd,  cudaFuncAttributeMaxDynamicSharedMemorySize, SMEM_FWD);
    cudaFuncSetAttribute(k_inv,  cudaFuncAttributeMaxDynamicSharedMemorySize, SMEM_INV);
    cudaFuncSetAttribute(k_conv, cudaFuncAttributeMaxDynamicSharedMemorySize, SMEM_CONV);

    k_init<<<64, 256>>>();
    k_tin<<<dim3(NFFT / 32, 32), dim3(32, 8)>>>(x);
    k_wt<<<dim3(16, 32), dim3(32, 8)>>>(wr, wi);
    k_fwd<<<1024, 512, SMEM_FWD>>>();
    k_einsum<<<512, 256>>>();
    k_conv<<<dim3(8, 32), dim3(32, 8), SMEM_CONV>>>(kr, ki);
    k_inv<<<1024, 512, SMEM_INV>>>();
    k_tout<<<dim3(NFFT / 32, 32), dim3(32, 8)>>>(out);
}

// round 8
// speedup vs baseline: 1.6798x; 1.3201x over previous
#include <cuda_runtime.h>
#include <math.h>

// SpectralConv1d_plus: B=32, N=16384, C_in=C_out=32, MODES=512, conv width 5.
// Pruned transform, now with an FFT inside:
//   N = 512*32; f = r + 32j (r<32, j<16), n = q + 512p, q = c + 32d (c<32, d<16).
// forward:  A[r][q] = sum_p x[q+512p] e^{-2pi i r p/32}
//           B[r][q] = A[r][q] e^{-2pi i r q/N}          (register rotator)
//           inner[c][j] = sum_d B[c+32d] e^{-2pi i jd/16}   (16-pt FFT, regs)
//           X[r+32j] = sum_c inner[c][j] e^{-2pi i jc/512}
// inverse (transpose):
//           E[c][j] = G[r+32j] e^{+2pi i jc/512}
//           u[c][d] = sum_j E[c][j] e^{+2pi i jd/16}        (16-pt inv FFT)
//           D[r][c+32d] = u[c][d] e^{+2pi i r(c+32d)/N}     (rotator)
//           y[m+512s] = sum_r Re( D[r][m] e^{+2pi i r s/32} )
// All normalizations fold into (f==0 ? 1 : 2)/N applied in k_conv.

#define NFFT   16384
#define MODES  512
#define FCONV  508

__device__ float2 g_tw[NFFT];                   // e^{+2pi i k/N}
__device__ float  g_xt[32 * 32 * NFFT];         // [b][c][n]
__device__ float2 g_Xf[32 * MODES * 32];        // [b][f][i]
__device__ float2 g_Wt[MODES * 32 * 32];        // [f][i][o]
__device__ float2 g_Y1[32 * MODES * 32];        // [b][f][o]
__device__ float2 g_G [32 * 32 * MODES];        // [b][o][f]
__device__ float  g_yt[32 * 32 * NFFT];         // [b][o][n]

#define SMEM_FWD  ((512 * 33 * 2 + 2048 + 1024) * 4)          // 147456 B
#define SMEM_INV  ((512 * 33 * 2 + 1056 + 1024 + 64) * 4)     // 143744 B
#define SMEM_CONV ((68 * 32 * 2 + 2 * 5120) * 4)              // 58368 B

// ---------------- 16-point complex FFT, fully in registers -----------------
// Computes V[j] = sum_d v[d] e^{SGN*2pi i jd/16}, natural order in/out.
template<int SGN>
__device__ __forceinline__ void fft16(float vr[16], float vi[16]) {
#define SWP(a,b) { float t_=vr[a]; vr[a]=vr[b]; vr[b]=t_; \
                   t_=vi[a]; vi[a]=vi[b]; vi[b]=t_; }
    SWP(1,8) SWP(2,4) SWP(3,12) SWP(5,10) SWP(7,14) SWP(11,13)
#undef SWP
#define BFLY(i0,i1,wr,wi) { \
    const float wr_ = (wr), wi_ = (float)SGN * (wi); \
    float tr_ = wr_*vr[i1] - wi_*vi[i1]; \
    float ti_ = wr_*vi[i1] + wi_*vr[i1]; \
    vr[i1] = vr[i0] - tr_; vi[i1] = vi[i0] - ti_; \
    vr[i0] += tr_;         vi[i0] += ti_; }
    // len=2
    BFLY(0,1,1.f,0.f)  BFLY(2,3,1.f,0.f)  BFLY(4,5,1.f,0.f)  BFLY(6,7,1.f,0.f)
    BFLY(8,9,1.f,0.f)  BFLY(10,11,1.f,0.f) BFLY(12,13,1.f,0.f) BFLY(14,15,1.f,0.f)
    // len=4: w = 1, (0,SGN)
    BFLY(0,2,1.f,0.f)  BFLY(1,3,0.f,1.f)
    BFLY(4,6,1.f,0.f)  BFLY(5,7,0.f,1.f)
    BFLY(8,10,1.f,0.f) BFLY(9,11,0.f,1.f)
    BFLY(12,14,1.f,0.f) BFLY(13,15,0.f,1.f)
    // len=8: w = e^{SGN 2pi i k/8}, k=0..3
    {
        const float C8 = 0.70710678118654752f;
        BFLY(0,4,1.f,0.f)  BFLY(1,5,C8,C8)  BFLY(2,6,0.f,1.f)  BFLY(3,7,-C8,C8)
        BFLY(8,12,1.f,0.f) BFLY(9,13,C8,C8) BFLY(10,14,0.f,1.f) BFLY(11,15,-C8,C8)
    }
    // len=16: w = e^{SGN 2pi i k/16}, k=0..7
    {
        const float C8 = 0.70710678118654752f;
        const float CA = 0.92387953251128674f, SA = 0.38268343236508977f;
        BFLY(0,8,1.f,0.f)   BFLY(1,9,CA,SA)    BFLY(2,10,C8,C8)  BFLY(3,11,SA,CA)
        BFLY(4,12,0.f,1.f)  BFLY(5,13,-SA,CA)  BFLY(6,14,-C8,C8) BFLY(7,15,-CA,SA)
    }
#undef BFLY
}

// --------------------------------- init -----------------------------------
__global__ void k_init() {
    int k = blockIdx.x * blockDim.x + threadIdx.x;   // 64*256 = 16384
    float s, c;
    sincospif((float)k / 8192.0f, &s, &c);           // angle = 2*pi*k/N
    g_tw[k] = make_float2(c, s);
}

// x [B,N,C] -> g_xt [B,C,N]
__global__ void k_tin(const float* __restrict__ x) {
    __shared__ float t[32][33];
    int tx = threadIdx.x, ty = threadIdx.y;
    int n0 = blockIdx.x * 32, b = blockIdx.y;
#pragma unroll
    for (int k = 0; k < 4; k++) {
        int row = ty + k * 8;
        t[row][tx] = x[((size_t)b * NFFT + n0 + row) * 32 + tx];
    }
    __syncthreads();
#pragma unroll
    for (int k = 0; k < 4; k++) {
        int c = ty + k * 8;
        g_xt[((size_t)b * 32 + c) * NFFT + n0 + tx] = t[tx][c];
    }
}

// w_real/w_imag [i][o][f] -> g_Wt[f][i*32+o] float2
__global__ void k_wt(const float* __restrict__ wr, const float* __restrict__ wi) {
    __shared__ float tr[32][33], ti[32][33];
    int tx = threadIdx.x, ty = threadIdx.y;
    int f0 = blockIdx.x * 32, io0 = blockIdx.y * 32;
#pragma unroll
    for (int k = 0; k < 4; k++) {
        int row = ty + k * 8;
        tr[row][tx] = wr[(io0 + row) * MODES + f0 + tx];
        ti[row][tx] = wi[(io0 + row) * MODES + f0 + tx];
    }
    __syncthreads();
#pragma unroll
    for (int k = 0; k < 4; k++) {
        int fr = ty + k * 8;
        g_Wt[(f0 + fr) * 1024 + io0 + tx] = make_float2(tr[tx][fr], ti[tx][fr]);
    }
}

// ------------------------------ forward DFT --------------------------------
// One block per signal (b*32+i). 512 threads / 16 warps, 1 CTA/SM.
__global__ __launch_bounds__(512, 1) void k_fwd() {
    extern __shared__ float smem[];
    float2* Bq   = (float2*)smem;          // [q][r] padded: 512*33      (135 KB)
    float2* Wtab = Bq + 512 * 33;          // [p][r]: e^{-2pi i r p/32}  (8 KB)
    float2* w512 = Wtab + 1024;            // e^{-2pi i t/512}           (4 KB)

    int sig = blockIdx.x, b = sig >> 5, ci = sig & 31;
    int tid = threadIdx.x, lane = tid & 31, w = tid >> 5;

    {
        float2 e = g_tw[(tid << 5) & (NFFT - 1)];
        w512[tid] = make_float2(e.x, -e.y);
    }
    for (int k = tid; k < 1024; k += 512) {
        int p = k >> 5, r = k & 31;
        float2 e = g_tw[((r * p) & 31) << 9];
        Wtab[k] = make_float2(e.x, -e.y);
    }
    __syncthreads();

    const float* xg = g_xt + (size_t)sig * NFFT;

    // ---- phase 1: stage A + N-twiddle -> Bq[q][r] in smem
    int q0 = w * 32;
    float2 e0 = g_tw[(lane * q0) & (NFFT - 1)];
    float tc = e0.x, ts = -e0.y;            // e^{-2pi i lane q0 / N}
    float2 ed = g_tw[lane];
    float dc = ed.x, ds = -ed.y;            // step e^{-2pi i lane / N}

    for (int g = 0; g < 8; g++) {
        int qq = q0 + g * 4;
        float ar[4] = {0.f,0.f,0.f,0.f}, ai[4] = {0.f,0.f,0.f,0.f};
#pragma unroll
        for (int p = 0; p < 32; p++) {
            float2 Wv = Wtab[(p << 5) + lane];                  // conflict-free LDS
            float4 xv = *(const float4*)(xg + qq + (p << 9));   // broadcast LDG
            ar[0] += xv.x * Wv.x; ai[0] += xv.x * Wv.y;
            ar[1] += xv.y * Wv.x; ai[1] += xv.y * Wv.y;
            ar[2] += xv.z * Wv.x; ai[2] += xv.z * Wv.y;
            ar[3] += xv.w * Wv.x; ai[3] += xv.w * Wv.y;
        }
#pragma unroll
        for (int t = 0; t < 4; t++) {
            Bq[(qq + t) * 33 + lane] =
                make_float2(ar[t] * tc - ai[t] * ts, ar[t] * ts + ai[t] * tc);
            float ntc = tc * dc - ts * ds, nts = tc * ds + ts * dc;
            tc = ntc; ts = nts;
        }
    }
    __syncthreads();

    // ---- phase 2: 16-pt FFT over d (q = c + 32d), in place, per (c, r=lane)
    for (int tt = 0; tt < 2; tt++) {
        int c = w + tt * 16;
        float vr[16], vi[16];
#pragma unroll
        for (int d = 0; d < 16; d++) {
            float2 bv = Bq[(c + (d << 5)) * 33 + lane];
            vr[d] = bv.x; vi[d] = bv.y;
        }
        fft16<-1>(vr, vi);
#pragma unroll
        for (int j = 0; j < 16; j++)
            Bq[(c + (j << 5)) * 33 + lane] = make_float2(vr[j], vi[j]);
    }
    __syncthreads();

    // ---- phase 3: combine over c. warp w -> j = w, lane = r.
    {
        int j = w;
        float xr = 0.f, xi = 0.f;
#pragma unroll 8
        for (int c = 0; c < 32; c++) {
            float2 bv = Bq[(c + (j << 5)) * 33 + lane];
            float2 wv = w512[(j * c) & 511];               // broadcast
            xr += bv.x * wv.x - bv.y * wv.y;
            xi += bv.x * wv.y + bv.y * wv.x;
        }
        g_Xf[((size_t)b * MODES + lane + (j << 5)) * 32 + ci] = make_float2(xr, xi);
    }
}

// ------------------------------ channel mix --------------------------------
__global__ void k_einsum() {
    __shared__ float2 Xs[1024];   // [b][i]
    __shared__ float2 Wsm[1024];  // [i][o]
    int f = blockIdx.x, tid = threadIdx.x;
    for (int k = tid; k < 1024; k += 256) {
        Wsm[k] = g_Wt[f * 1024 + k];
        int bb = k >> 5, ii = k & 31;
        Xs[k] = g_Xf[((size_t)bb * MODES + f) * 32 + ii];
    }
    __syncthreads();
    int o = tid & 31, bg = tid >> 5;
    for (int bb = bg; bb < 32; bb += 8) {
        float yr = 0.f, yi = 0.f;
#pragma unroll
        for (int ii = 0; ii < 32; ii++) {
            float2 xv = Xs[bb * 32 + ii];
            float2 wv = Wsm[ii * 32 + o];
            yr += xv.x * wv.x - xv.y * wv.y;
            yi += xv.x * wv.y + xv.y * wv.x;
        }
        g_Y1[((size_t)bb * MODES + f) * 32 + o] = make_float2(yr, yi);
    }
}

// ----------------------------- frequency conv ------------------------------
__global__ void k_conv(const float* __restrict__ kre, const float* __restrict__ kim) {
    extern __shared__ float cs[];
    float2* Ys  = (float2*)cs;            // 68*32
    float*  krs = cs + 68 * 32 * 2;       // 5120
    float*  kis = krs + 5120;             // 5120
    int tx = threadIdx.x, ty = threadIdx.y;
    int tid = ty * 32 + tx;
    int b = blockIdx.y, f0 = blockIdx.x * 64;
    int nrows = min(68, 512 - f0);
    for (int k = tid; k < nrows * 32; k += 256)
        Ys[k] = g_Y1[((size_t)b * MODES + f0) * 32 + k];
    for (int k = tid; k < 5120; k += 256) { krs[k] = kre[k]; kis[k] = kim[k]; }
    __syncthreads();
    for (int c8 = 0; c8 < 8; c8++) {
        int fl = ty * 8 + c8;
        int f = f0 + fl;
        float gr = 0.f, gi = 0.f;
        if (f < FCONV) {
#pragma unroll
            for (int w5 = 0; w5 < 5; w5++)
#pragma unroll
                for (int c = 0; c < 32; c++) {
                    float2 yv = Ys[(fl + w5) * 32 + c];
                    gr += yv.x * krs[(w5 * 32 + c) * 32 + tx];
                    gi += yv.y * kis[(w5 * 32 + c) * 32 + tx];
                }
            float sc = (f == 0) ? (1.0f / NFFT) : (2.0f / NFFT);
            gr *= sc; gi *= sc;
        }
        g_G[((size_t)b * 32 + tx) * MODES + f] = make_float2(gr, gi);
    }
}

// ------------------------------ inverse DFT --------------------------------
// One block per signal. 512 threads, 1 CTA/SM.
__global__ __launch_bounds__(512, 1) void k_inv() {
    extern __shared__ float smem[];
    float*  Dre   = smem;                        // [512][33]
    float*  Dim   = Dre + 512 * 33;              // [512][33]
    float2* Gs    = (float2*)(Dim + 512 * 33);   // [j][33] padded (528)
    float2* w512p = Gs + 528;                    // e^{+2pi i t/512}
    float2* cs32  = w512p + 512;                 // e^{+2pi i t/32}

    int sig = blockIdx.x;
    int tid = threadIdx.x, lane = tid & 31, w = tid >> 5;

    w512p[tid] = g_tw[(tid << 5) & (NFFT - 1)];
    if (tid < 32) cs32[tid] = g_tw[tid << 9];
    {   // G -> smem [j][r] padded; f = tid: r = tid&31, j = tid>>5
        float2 gv = g_G[(size_t)sig * MODES + tid];
        Gs[(tid >> 5) * 33 + (tid & 31)] = gv;
    }
    __syncthreads();

    // ---- phase A: per task (c, r=lane): twiddle + 16-pt inverse FFT + N-twiddle
    for (int tt = 0; tt < 2; tt++) {
        int c = w + tt * 16;
        float vr[16], vi[16];
#pragma unroll
        for (int j = 0; j < 16; j++) {
            float2 gv = Gs[j * 33 + lane];
            float2 wv = w512p[(j * c) & 511];          // broadcast
            vr[j] = gv.x * wv.x - gv.y * wv.y;
            vi[j] = gv.x * wv.y + gv.y * wv.x;
        }
        fft16<+1>(vr, vi);                              // j -> d
        float2 t0 = g_tw[(lane * c) & (NFFT - 1)];      // e^{+2pi i r c/N}
        float2 st = w512p[lane];                        // e^{+2pi i r/512}
        float tc = t0.x, ts = t0.y;
#pragma unroll
        for (int d = 0; d < 16; d++) {
            int m = c + (d << 5);
            Dre[m * 33 + lane] = vr[d] * tc - vi[d] * ts;
            Dim[m * 33 + lane] = vr[d] * ts + vi[d] * tc;
            float ntc = tc * st.x - ts * st.y, nts = tc * st.y + ts * st.x;
            tc = ntc; ts = nts;
        }
    }
    __syncthreads();

    // ---- phase B: 32-pt synthesis; thread -> m = tid, both s-halves
    for (int h = 0; h < 2; h++) {
        int s0 = h << 4;
        float y[16];
#pragma unroll
        for (int k = 0; k < 16; k++) y[k] = 0.f;
#pragma unroll
        for (int r = 0; r < 32; r++) {
            float dr = Dre[tid * 33 + r], di = Dim[tid * 33 + r];
            int base = r * s0;
#pragma unroll
            for (int k = 0; k < 8; k++) {
                float2 cv = cs32[(base + r * k) & 31];
                float tpos = dr * cv.x - di * cv.y;
                y[k] += tpos;
                // s+8 term: twiddle multiplied by i^r (compile-time folded)
                if ((r & 3) == 0)      y[k + 8] += tpos;
                else if ((r & 3) == 1) y[k + 8] -= dr * cv.y + di * cv.x;
                else if ((r & 3) == 2) y[k + 8] -= tpos;
                else                   y[k + 8] += dr * cv.y + di * cv.x;
            }
        }
        float* yo = g_yt + (size_t)sig * NFFT + tid;
#pragma unroll
        for (int k = 0; k < 16; k++)
            yo[(size_t)(s0 + k) << 9] = y[k];   // coalesced per s
    }
}

// g_yt [B,C,N] -> out [B,N,C]
__global__ void k_tout(float* __restrict__ out) {
    __shared__ float t[32][33];
    int tx = threadIdx.x, ty = threadIdx.y;
    int n0 = blockIdx.x * 32, b = blockIdx.y;
#pragma unroll
    for (int k = 0; k < 4; k++) {
        int c = ty + k * 8;
        t[c][tx] = g_yt[((size_t)b * 32 + c) * NFFT + n0 + tx];
    }
    __syncthreads();
#pragma unroll
    for (int k = 0; k < 4; k++) {
        int row = ty + k * 8;
        out[((size_t)b * NFFT + n0 + row) * 32 + tx] = t[tx][row];
    }
}

extern "C" void kernel_launch(void* const* d_in, const int* in_sizes, int n_in,
                              void* d_out, int out_size) {
    const float* x  = (const float*)d_in[0];
    const float* wr = (const float*)d_in[1];
    const float* wi = (const float*)d_in[2];
    const float* kr = (const float*)d_in[3];
    const float* ki = (const float*)d_in[4];
    float* out = (float*)d_out;

    cudaFuncSetAttribute(k_fwd,  cudaFuncAttributeMaxDynamicSharedMemorySize, SMEM_FWD);
    cudaFuncSetAttribute(k_inv,  cudaFuncAttributeMaxDynamicSharedMemorySize, SMEM_INV);
    cudaFuncSetAttribute(k_conv, cudaFuncAttributeMaxDynamicSharedMemorySize, SMEM_CONV);

    k_init<<<64, 256>>>();
    k_tin<<<dim3(NFFT / 32, 32), dim3(32, 8)>>>(x);
    k_wt<<<dim3(16, 32), dim3(32, 8)>>>(wr, wi);
    k_fwd<<<1024, 512, SMEM_FWD>>>();
    k_einsum<<<512, 256>>>();
    k_conv<<<dim3(8, 32), dim3(32, 8), SMEM_CONV>>>(kr, ki);
    k_inv<<<1024, 512, SMEM_INV>>>();
    k_tout<<<dim3(NFFT / 32, 32), dim3(32, 8)>>>(out);
}

// round 10
// speedup vs baseline: 1.9931x; 1.1865x over previous
#include <cuda_runtime.h>
#include <math.h>

// SpectralConv1d_plus: B=32, N=16384, C_in=C_out=32, MODES=512, conv width 5.
// Pruned transform with internal 16-pt FFT:
//   N = 512*32; f = r + 32j (r<32, j<16), n = q + 512p, q = c + 32d (c<32, d<16).
// forward:  A[r][q] = sum_p x[q+512p] e^{-2pi i r p/32}       (reg W row)
//           B[r][q] = A[r][q] e^{-2pi i r q/N}                (register rotator)
//           inner[c][j] = sum_d B[c+32d] e^{-2pi i jd/16}     (16-pt FFT, regs)
//           X[r+32j] = sum_c inner[c][j] e^{-2pi i jc/512}
// inverse (transpose):
//           E[c][j] = G[r+32j] e^{+2pi i jc/512}
//           u[c][d] = sum_j E[c][j] e^{+2pi i jd/16}          (16-pt inv FFT)
//           D[r][c+32d] = u[c][d] e^{+2pi i r(c+32d)/N}       (rotator)
//           y[m+512s] = Re( 32-pt FFT_s of D[.][m] )          (2x fft16 + combine)
// All normalizations fold into (f==0 ? 1 : 2)/N applied in k_conv.
// R8 lesson: Wtab in smem put 512 LDS-wavefronts/warp in the hot loop
// (L1=84.9%); W row lives in registers again this round.

#define NFFT   16384
#define MODES  512
#define FCONV  508

__device__ float2 g_tw[NFFT];                   // e^{+2pi i k/N}
__device__ float  g_xt[32 * 32 * NFFT];         // [b][c][n]
__device__ float2 g_Xf[32 * MODES * 32];        // [b][f][i]
__device__ float2 g_Wt[MODES * 32 * 32];        // [f][i][o]
__device__ float2 g_Y1[32 * MODES * 32];        // [b][f][o]
__device__ float2 g_G [32 * 32 * MODES];        // [b][o][f]
__device__ float  g_yt[32 * 32 * NFFT];         // [b][o][n]

#define SMEM_FWD  ((512 * 33 * 2 + 1024) * 4)                 // 139264 B
#define SMEM_INV  ((512 * 33 * 2 + 1056 + 1024 + 64) * 4)     // 143744 B
#define SMEM_CONV ((68 * 32 * 2 + 2 * 5120) * 4)              // 58368 B

// ---------------- 16-point complex FFT, fully in registers -----------------
// Computes V[j] = sum_d v[d] e^{SGN*2pi i jd/16}, natural order in/out.
template<int SGN>
__device__ __forceinline__ void fft16(float vr[16], float vi[16]) {
#define SWP(a,b) { float t_=vr[a]; vr[a]=vr[b]; vr[b]=t_; \
                   t_=vi[a]; vi[a]=vi[b]; vi[b]=t_; }
    SWP(1,8) SWP(2,4) SWP(3,12) SWP(5,10) SWP(7,14) SWP(11,13)
#undef SWP
#define BFLY(i0,i1,wr,wi) { \
    const float wr_ = (wr), wi_ = (float)SGN * (wi); \
    float tr_ = wr_*vr[i1] - wi_*vi[i1]; \
    float ti_ = wr_*vi[i1] + wi_*vr[i1]; \
    vr[i1] = vr[i0] - tr_; vi[i1] = vi[i0] - ti_; \
    vr[i0] += tr_;         vi[i0] += ti_; }
    // len=2
    BFLY(0,1,1.f,0.f)  BFLY(2,3,1.f,0.f)  BFLY(4,5,1.f,0.f)  BFLY(6,7,1.f,0.f)
    BFLY(8,9,1.f,0.f)  BFLY(10,11,1.f,0.f) BFLY(12,13,1.f,0.f) BFLY(14,15,1.f,0.f)
    // len=4: w = 1, (0,SGN)
    BFLY(0,2,1.f,0.f)  BFLY(1,3,0.f,1.f)
    BFLY(4,6,1.f,0.f)  BFLY(5,7,0.f,1.f)
    BFLY(8,10,1.f,0.f) BFLY(9,11,0.f,1.f)
    BFLY(12,14,1.f,0.f) BFLY(13,15,0.f,1.f)
    // len=8: w = e^{SGN 2pi i k/8}, k=0..3
    {
        const float C8 = 0.70710678118654752f;
        BFLY(0,4,1.f,0.f)  BFLY(1,5,C8,C8)  BFLY(2,6,0.f,1.f)  BFLY(3,7,-C8,C8)
        BFLY(8,12,1.f,0.f) BFLY(9,13,C8,C8) BFLY(10,14,0.f,1.f) BFLY(11,15,-C8,C8)
    }
    // len=16: w = e^{SGN 2pi i k/16}, k=0..7
    {
        const float C8 = 0.70710678118654752f;
        const float CA = 0.92387953251128674f, SA = 0.38268343236508977f;
        BFLY(0,8,1.f,0.f)   BFLY(1,9,CA,SA)    BFLY(2,10,C8,C8)  BFLY(3,11,SA,CA)
        BFLY(4,12,0.f,1.f)  BFLY(5,13,-SA,CA)  BFLY(6,14,-C8,C8) BFLY(7,15,-CA,SA)
    }
#undef BFLY
}

// --------------------------------- init -----------------------------------
__global__ void k_init() {
    int k = blockIdx.x * blockDim.x + threadIdx.x;   // 64*256 = 16384
    float s, c;
    sincospif((float)k / 8192.0f, &s, &c);           // angle = 2*pi*k/N
    g_tw[k] = make_float2(c, s);
}

// x [B,N,C] -> g_xt [B,C,N]
__global__ void k_tin(const float* __restrict__ x) {
    __shared__ float t[32][33];
    int tx = threadIdx.x, ty = threadIdx.y;
    int n0 = blockIdx.x * 32, b = blockIdx.y;
#pragma unroll
    for (int k = 0; k < 4; k++) {
        int row = ty + k * 8;
        t[row][tx] = x[((size_t)b * NFFT + n0 + row) * 32 + tx];
    }
    __syncthreads();
#pragma unroll
    for (int k = 0; k < 4; k++) {
        int c = ty + k * 8;
        g_xt[((size_t)b * 32 + c) * NFFT + n0 + tx] = t[tx][c];
    }
}

// w_real/w_imag [i][o][f] -> g_Wt[f][i*32+o] float2
__global__ void k_wt(const float* __restrict__ wr, const float* __restrict__ wi) {
    __shared__ float tr[32][33], ti[32][33];
    int tx = threadIdx.x, ty = threadIdx.y;
    int f0 = blockIdx.x * 32, io0 = blockIdx.y * 32;
#pragma unroll
    for (int k = 0; k < 4; k++) {
        int row = ty + k * 8;
        tr[row][tx] = wr[(io0 + row) * MODES + f0 + tx];
        ti[row][tx] = wi[(io0 + row) * MODES + f0 + tx];
    }
    __syncthreads();
#pragma unroll
    for (int k = 0; k < 4; k++) {
        int fr = ty + k * 8;
        g_Wt[(f0 + fr) * 1024 + io0 + tx] = make_float2(tr[tx][fr], ti[tx][fr]);
    }
}

// ------------------------------ forward DFT --------------------------------
// One block per signal (b*32+i). 512 threads / 16 warps, 1 CTA/SM.
__global__ __launch_bounds__(512, 1) void k_fwd() {
    extern __shared__ float smem[];
    float2* Bq   = (float2*)smem;          // [q][r] padded: 512*33    (135 KB)
    float2* w512 = Bq + 512 * 33;          // e^{-2pi i t/512}         (4 KB)

    int sig = blockIdx.x, b = sig >> 5, ci = sig & 31;
    int tid = threadIdx.x, lane = tid & 31, w = tid >> 5;

    {
        float2 e = g_tw[(tid << 5) & (NFFT - 1)];
        w512[tid] = make_float2(e.x, -e.y);
    }
    // per-lane 32-pt DFT row (r = lane): e^{-2pi i r p/32}, in registers
    float Wc[32], Ws[32];
#pragma unroll
    for (int p = 0; p < 32; p++) {
        float2 e = g_tw[((lane * p) & 31) << 9];
        Wc[p] = e.x; Ws[p] = -e.y;
    }
    __syncthreads();

    const float* xg = g_xt + (size_t)sig * NFFT;

    // ---- phase 1: stage A + N-twiddle -> Bq[q][r] in smem
    int q0 = w * 32;
    float2 e0 = g_tw[(lane * q0) & (NFFT - 1)];
    float tc = e0.x, ts = -e0.y;            // e^{-2pi i lane q0 / N}
    float2 ed = g_tw[lane];
    float dc = ed.x, ds = -ed.y;            // step e^{-2pi i lane / N}

    for (int g = 0; g < 8; g++) {
        int qq = q0 + g * 4;
        float ar[4] = {0.f,0.f,0.f,0.f}, ai[4] = {0.f,0.f,0.f,0.f};
#pragma unroll
        for (int p = 0; p < 32; p++) {
            float4 xv = *(const float4*)(xg + qq + (p << 9));   // broadcast LDG
            ar[0] += xv.x * Wc[p]; ai[0] += xv.x * Ws[p];
            ar[1] += xv.y * Wc[p]; ai[1] += xv.y * Ws[p];
            ar[2] += xv.z * Wc[p]; ai[2] += xv.z * Ws[p];
            ar[3] += xv.w * Wc[p]; ai[3] += xv.w * Ws[p];
        }
#pragma unroll
        for (int t = 0; t < 4; t++) {
            Bq[(qq + t) * 33 + lane] =
                make_float2(ar[t] * tc - ai[t] * ts, ar[t] * ts + ai[t] * tc);
            float ntc = tc * dc - ts * ds, nts = tc * ds + ts * dc;
            tc = ntc; ts = nts;
        }
    }
    __syncthreads();

    // ---- phase 2: 16-pt FFT over d (q = c + 32d), in place, per (c, r=lane)
    for (int tt = 0; tt < 2; tt++) {
        int c = w + tt * 16;
        float vr[16], vi[16];
#pragma unroll
        for (int d = 0; d < 16; d++) {
            float2 bv = Bq[(c + (d << 5)) * 33 + lane];
            vr[d] = bv.x; vi[d] = bv.y;
        }
        fft16<-1>(vr, vi);
#pragma unroll
        for (int j = 0; j < 16; j++)
            Bq[(c + (j << 5)) * 33 + lane] = make_float2(vr[j], vi[j]);
    }
    __syncthreads();

    // ---- phase 3: combine over c. warp w -> j = w, lane = r.
    {
        int j = w;
        float xr = 0.f, xi = 0.f;
#pragma unroll 8
        for (int c = 0; c < 32; c++) {
            float2 bv = Bq[(c + (j << 5)) * 33 + lane];
            float2 wv = w512[(j * c) & 511];               // broadcast
            xr += bv.x * wv.x - bv.y * wv.y;
            xi += bv.x * wv.y + bv.y * wv.x;
        }
        g_Xf[((size_t)b * MODES + lane + (j << 5)) * 32 + ci] = make_float2(xr, xi);
    }
}

// ------------------------------ channel mix --------------------------------
__global__ void k_einsum() {
    __shared__ float2 Xs[1024];   // [b][i]
    __shared__ float2 Wsm[1024];  // [i][o]
    int f = blockIdx.x, tid = threadIdx.x;
    for (int k = tid; k < 1024; k += 256) {
        Wsm[k] = g_Wt[f * 1024 + k];
        int bb = k >> 5, ii = k & 31;
        Xs[k] = g_Xf[((size_t)bb * MODES + f) * 32 + ii];
    }
    __syncthreads();
    int o = tid & 31, bg = tid >> 5;
    for (int bb = bg; bb < 32; bb += 8) {
        float yr = 0.f, yi = 0.f;
#pragma unroll
        for (int ii = 0; ii < 32; ii++) {
            float2 xv = Xs[bb * 32 + ii];
            float2 wv = Wsm[ii * 32 + o];
            yr += xv.x * wv.x - xv.y * wv.y;
            yi += xv.x * wv.y + xv.y * wv.x;
        }
        g_Y1[((size_t)bb * MODES + f) * 32 + o] = make_float2(yr, yi);
    }
}

// ----------------------------- frequency conv ------------------------------
__global__ void k_conv(const float* __restrict__ kre, const float* __restrict__ kim) {
    extern __shared__ float cs[];
    float2* Ys  = (float2*)cs;            // 68*32
    float*  krs = cs + 68 * 32 * 2;       // 5120
    float*  kis = krs + 5120;             // 5120
    int tx = threadIdx.x, ty = threadIdx.y;
    int tid = ty * 32 + tx;
    int b = blockIdx.y, f0 = blockIdx.x * 64;
    int nrows = min(68, 512 - f0);
    for (int k = tid; k < nrows * 32; k += 256)
        Ys[k] = g_Y1[((size_t)b * MODES + f0) * 32 + k];
    for (int k = tid; k < 5120; k += 256) { krs[k] = kre[k]; kis[k] = kim[k]; }
    __syncthreads();
    for (int c8 = 0; c8 < 8; c8++) {
        int fl = ty * 8 + c8;
        int f = f0 + fl;
        float gr = 0.f, gi = 0.f;
        if (f < FCONV) {
#pragma unroll
            for (int w5 = 0; w5 < 5; w5++)
#pragma unroll
                for (int c = 0; c < 32; c++) {
                    float2 yv = Ys[(fl + w5) * 32 + c];
                    gr += yv.x * krs[(w5 * 32 + c) * 32 + tx];
                    gi += yv.y * kis[(w5 * 32 + c) * 32 + tx];
                }
            float sc = (f == 0) ? (1.0f / NFFT) : (2.0f / NFFT);
            gr *= sc; gi *= sc;
        }
        g_G[((size_t)b * 32 + tx) * MODES + f] = make_float2(gr, gi);
    }
}

// ------------------------------ inverse DFT --------------------------------
// One block per signal. 512 threads, 1 CTA/SM.
__global__ __launch_bounds__(512, 1) void k_inv() {
    extern __shared__ float smem[];
    float*  Dre   = smem;                        // [512][33]
    float*  Dim   = Dre + 512 * 33;              // [512][33]
    float2* Gs    = (float2*)(Dim + 512 * 33);   // [j][33] padded (528)
    float2* w512p = Gs + 528;                    // e^{+2pi i t/512}
    float2* cs32  = w512p + 512;                 // (kept for layout)

    int sig = blockIdx.x;
    int tid = threadIdx.x, lane = tid & 31, w = tid >> 5;

    w512p[tid] = g_tw[(tid << 5) & (NFFT - 1)];
    if (tid < 32) cs32[tid] = g_tw[tid << 9];
    {   // G -> smem [j][r] padded; f = tid: r = tid&31, j = tid>>5
        float2 gv = g_G[(size_t)sig * MODES + tid];
        Gs[(tid >> 5) * 33 + (tid & 31)] = gv;
    }
    __syncthreads();

    // ---- phase A: per task (c, r=lane): twiddle + 16-pt inverse FFT + N-twiddle
    for (int tt = 0; tt < 2; tt++) {
        int c = w + tt * 16;
        float vr[16], vi[16];
#pragma unroll
        for (int j = 0; j < 16; j++) {
            float2 gv = Gs[j * 33 + lane];
            float2 wv = w512p[(j * c) & 511];          // broadcast
            vr[j] = gv.x * wv.x - gv.y * wv.y;
            vi[j] = gv.x * wv.y + gv.y * wv.x;
        }
        fft16<+1>(vr, vi);                              // j -> d
        float2 t0 = g_tw[(lane * c) & (NFFT - 1)];      // e^{+2pi i r c/N}
        float2 st = w512p[lane];                        // e^{+2pi i r/512}
        float tc = t0.x, ts = t0.y;
#pragma unroll
        for (int d = 0; d < 16; d++) {
            int m = c + (d << 5);
            Dre[m * 33 + lane] = vr[d] * tc - vi[d] * ts;
            Dim[m * 33 + lane] = vr[d] * ts + vi[d] * tc;
            float ntc = tc * st.x - ts * st.y, nts = tc * st.y + ts * st.x;
            tc = ntc; ts = nts;
        }
    }
    __syncthreads();

    // ---- phase B: 32-pt synthesis via 2x fft16 (DIT split).
    // y[s] = Re( sum_r D[r] e^{+2pi i r s/32} ):
    //   E = fft16(+1) of D[even r], O = fft16(+1) of D[odd r];
    //   y[k] = Er[k] + Re(w32^k O[k]); y[k+16] = Er[k] - Re(w32^k O[k]).
    {
        const float W32R[16] = {
            1.f,                    0.98078528040323044913f, 0.92387953251128675613f,
            0.83146961230254523708f, 0.70710678118654752440f, 0.55557023301960222474f,
            0.38268343236508977173f, 0.19509032201612826785f, 0.f,
            -0.19509032201612826785f, -0.38268343236508977173f, -0.55557023301960222474f,
            -0.70710678118654752440f, -0.83146961230254523708f, -0.92387953251128675613f,
            -0.98078528040323044913f };
        const float W32I[16] = {
            0.f,                    0.19509032201612826785f, 0.38268343236508977173f,
            0.55557023301960222474f, 0.70710678118654752440f, 0.83146961230254523708f,
            0.92387953251128675613f, 0.98078528040323044913f, 1.f,
            0.98078528040323044913f, 0.92387953251128675613f, 0.83146961230254523708f,
            0.70710678118654752440f, 0.55557023301960222474f, 0.38268343236508977173f,
            0.19509032201612826785f };
        float er[16], ei[16], odr[16], odi[16];
#pragma unroll
        for (int d = 0; d < 16; d++) {
            er[d]  = Dre[tid * 33 + 2 * d];     ei[d]  = Dim[tid * 33 + 2 * d];
            odr[d] = Dre[tid * 33 + 2 * d + 1]; odi[d] = Dim[tid * 33 + 2 * d + 1];
        }
        fft16<+1>(er, ei);
        fft16<+1>(odr, odi);
        float* yo = g_yt + (size_t)sig * NFFT + tid;   // m = tid; coalesced per s
#pragma unroll
        for (int k = 0; k < 16; k++) {
            float t = W32R[k] * odr[k] - W32I[k] * odi[k];
            yo[(size_t)k << 9]        = er[k] + t;
            yo[(size_t)(k + 16) << 9] = er[k] - t;
        }
    }
}

// g_yt [B,C,N] -> out [B,N,C]
__global__ void k_tout(float* __restrict__ out) {
    __shared__ float t[32][33];
    int tx = threadIdx.x, ty = threadIdx.y;
    int n0 = blockIdx.x * 32, b = blockIdx.y;
#pragma unroll
    for (int k = 0; k < 4; k++) {
        int c = ty + k * 8;
        t[c][tx] = g_yt[((size_t)b * 32 + c) * NFFT + n0 + tx];
    }
    __syncthreads();
#pragma unroll
    for (int k = 0; k < 4; k++) {
        int row = ty + k * 8;
        out[((size_t)b * NFFT + n0 + row) * 32 + tx] = t[tx][row];
    }
}

extern "C" void kernel_launch(void* const* d_in, const int* in_sizes, int n_in,
                              void* d_out, int out_size) {
    const float* x  = (const float*)d_in[0];
    const float* wr = (const float*)d_in[1];
    const float* wi = (const float*)d_in[2];
    const float* kr = (const float*)d_in[3];
    const float* ki = (const float*)d_in[4];
    float* out = (float*)d_out;

    cudaFuncSetAttribute(k_fwd,  cudaFuncAttributeMaxDynamicSharedMemorySize, SMEM_FWD);
    cudaFuncSetAttribute(k_inv,  cudaFuncAttributeMaxDynamicSharedMemorySize, SMEM_INV);
    cudaFuncSetAttribute(k_conv, cudaFuncAttributeMaxDynamicSharedMemorySize, SMEM_CONV);

    k_init<<<64, 256>>>();
    k_tin<<<dim3(NFFT / 32, 32), dim3(32, 8)>>>(x);
    k_wt<<<dim3(16, 32), dim3(32, 8)>>>(wr, wi);
    k_fwd<<<1024, 512, SMEM_FWD>>>();
    k_einsum<<<512, 256>>>();
    k_conv<<<dim3(8, 32), dim3(32, 8), SMEM_CONV>>>(kr, ki);
    k_inv<<<1024, 512, SMEM_INV>>>();
    k_tout<<<dim3(NFFT / 32, 32), dim3(32, 8)>>>(out);
}

// round 11
// speedup vs baseline: 2.3359x; 1.1720x over previous
#include <cuda_runtime.h>
#include <math.h>

// SpectralConv1d_plus: B=32, N=16384, C_in=C_out=32, MODES=512, conv width 5.
// Pruned transform with internal 16-pt FFT:
//   N = 512*32; f = r + 32j (r<32, j<16), n = q + 512p, q = c + 32d (c<32, d<16).
// forward:  A[r][q] = sum_p x[q+512p] e^{-2pi i r p/32}
//           B[r][q] = A[r][q] e^{-2pi i r q/N}                (register rotator)
//           inner[c][j] = sum_d B[c+32d] e^{-2pi i jd/16}     (16-pt FFT, regs)
//           X[r+32j] = sum_c inner[c][j] e^{-2pi i jc/512}
// inverse (transpose):
//           E[c][j] = G[r+32j] e^{+2pi i jc/512}
//           u[c][d] = sum_j E[c][j] e^{+2pi i jd/16}          (16-pt inv FFT)
//           D[r][c+32d] = u[c][d] e^{+2pi i r(c+32d)/N}       (rotator)
//           y[m+512s] = Re( 32-pt FFT_s of D[.][m] )          (2x fft16 + combine)
// All normalizations fold into (f==0 ? 1 : 2)/N applied in k_conv.
// R10 lesson: W row in registers (64 regs) starved load pipelining (issue
// 42.9->34.5%, 132->162us). This round: W stays in smem (R8 config) but the
// phase-1 loops are interchanged (16-q passes) so Wtab is read 64x/warp
// instead of 256x/warp.

#define NFFT   16384
#define MODES  512
#define FCONV  508

__device__ float2 g_tw[NFFT];                   // e^{+2pi i k/N}
__device__ float  g_xt[32 * 32 * NFFT];         // [b][c][n]
__device__ float2 g_Xf[32 * MODES * 32];        // [b][f][i]
__device__ float2 g_Wt[MODES * 32 * 32];        // [f][i][o]
__device__ float2 g_Y1[32 * MODES * 32];        // [b][f][o]
__device__ float2 g_G [32 * 32 * MODES];        // [b][o][f]
__device__ float  g_yt[32 * 32 * NFFT];         // [b][o][n]

#define SMEM_FWD  ((512 * 33 * 2 + 2048 + 1024) * 4)          // 147456 B
#define SMEM_INV  ((512 * 33 * 2 + 1056 + 1024 + 64) * 4)     // 143744 B
#define SMEM_CONV ((68 * 32 * 2 + 2 * 5120) * 4)              // 58368 B

// ---------------- 16-point complex FFT, fully in registers -----------------
// Computes V[j] = sum_d v[d] e^{SGN*2pi i jd/16}, natural order in/out.
template<int SGN>
__device__ __forceinline__ void fft16(float vr[16], float vi[16]) {
#define SWP(a,b) { float t_=vr[a]; vr[a]=vr[b]; vr[b]=t_; \
                   t_=vi[a]; vi[a]=vi[b]; vi[b]=t_; }
    SWP(1,8) SWP(2,4) SWP(3,12) SWP(5,10) SWP(7,14) SWP(11,13)
#undef SWP
#define BFLY(i0,i1,wr,wi) { \
    const float wr_ = (wr), wi_ = (float)SGN * (wi); \
    float tr_ = wr_*vr[i1] - wi_*vi[i1]; \
    float ti_ = wr_*vi[i1] + wi_*vr[i1]; \
    vr[i1] = vr[i0] - tr_; vi[i1] = vi[i0] - ti_; \
    vr[i0] += tr_;         vi[i0] += ti_; }
    // len=2
    BFLY(0,1,1.f,0.f)  BFLY(2,3,1.f,0.f)  BFLY(4,5,1.f,0.f)  BFLY(6,7,1.f,0.f)
    BFLY(8,9,1.f,0.f)  BFLY(10,11,1.f,0.f) BFLY(12,13,1.f,0.f) BFLY(14,15,1.f,0.f)
    // len=4: w = 1, (0,SGN)
    BFLY(0,2,1.f,0.f)  BFLY(1,3,0.f,1.f)
    BFLY(4,6,1.f,0.f)  BFLY(5,7,0.f,1.f)
    BFLY(8,10,1.f,0.f) BFLY(9,11,0.f,1.f)
    BFLY(12,14,1.f,0.f) BFLY(13,15,0.f,1.f)
    // len=8: w = e^{SGN 2pi i k/8}, k=0..3
    {
        const float C8 = 0.70710678118654752f;
        BFLY(0,4,1.f,0.f)  BFLY(1,5,C8,C8)  BFLY(2,6,0.f,1.f)  BFLY(3,7,-C8,C8)
        BFLY(8,12,1.f,0.f) BFLY(9,13,C8,C8) BFLY(10,14,0.f,1.f) BFLY(11,15,-C8,C8)
    }
    // len=16: w = e^{SGN 2pi i k/16}, k=0..7
    {
        const float C8 = 0.70710678118654752f;
        const float CA = 0.92387953251128674f, SA = 0.38268343236508977f;
        BFLY(0,8,1.f,0.f)   BFLY(1,9,CA,SA)    BFLY(2,10,C8,C8)  BFLY(3,11,SA,CA)
        BFLY(4,12,0.f,1.f)  BFLY(5,13,-SA,CA)  BFLY(6,14,-C8,C8) BFLY(7,15,-CA,SA)
    }
#undef BFLY
}

// --------------------------------- init -----------------------------------
__global__ void k_init() {
    int k = blockIdx.x * blockDim.x + threadIdx.x;   // 64*256 = 16384
    float s, c;
    sincospif((float)k / 8192.0f, &s, &c);           // angle = 2*pi*k/N
    g_tw[k] = make_float2(c, s);
}

// x [B,N,C] -> g_xt [B,C,N]
__global__ void k_tin(const float* __restrict__ x) {
    __shared__ float t[32][33];
    int tx = threadIdx.x, ty = threadIdx.y;
    int n0 = blockIdx.x * 32, b = blockIdx.y;
#pragma unroll
    for (int k = 0; k < 4; k++) {
        int row = ty + k * 8;
        t[row][tx] = x[((size_t)b * NFFT + n0 + row) * 32 + tx];
    }
    __syncthreads();
#pragma unroll
    for (int k = 0; k < 4; k++) {
        int c = ty + k * 8;
        g_xt[((size_t)b * 32 + c) * NFFT + n0 + tx] = t[tx][c];
    }
}

// w_real/w_imag [i][o][f] -> g_Wt[f][i*32+o] float2
__global__ void k_wt(const float* __restrict__ wr, const float* __restrict__ wi) {
    __shared__ float tr[32][33], ti[32][33];
    int tx = threadIdx.x, ty = threadIdx.y;
    int f0 = blockIdx.x * 32, io0 = blockIdx.y * 32;
#pragma unroll
    for (int k = 0; k < 4; k++) {
        int row = ty + k * 8;
        tr[row][tx] = wr[(io0 + row) * MODES + f0 + tx];
        ti[row][tx] = wi[(io0 + row) * MODES + f0 + tx];
    }
    __syncthreads();
#pragma unroll
    for (int k = 0; k < 4; k++) {
        int fr = ty + k * 8;
        g_Wt[(f0 + fr) * 1024 + io0 + tx] = make_float2(tr[tx][fr], ti[tx][fr]);
    }
}

// ------------------------------ forward DFT --------------------------------
// One block per signal (b*32+i). 512 threads / 16 warps, 1 CTA/SM.
__global__ __launch_bounds__(512, 1) void k_fwd() {
    extern __shared__ float smem[];
    float2* Bq   = (float2*)smem;          // [q][r] padded: 512*33    (135 KB)
    float2* Wtab = Bq + 512 * 33;          // [p][r]: e^{-2pi i r p/32} (8 KB)
    float2* w512 = Wtab + 1024;            // e^{-2pi i t/512}          (4 KB)

    int sig = blockIdx.x, b = sig >> 5, ci = sig & 31;
    int tid = threadIdx.x, lane = tid & 31, w = tid >> 5;

    {
        float2 e = g_tw[(tid << 5) & (NFFT - 1)];
        w512[tid] = make_float2(e.x, -e.y);
    }
    for (int k = tid; k < 1024; k += 512) {
        int p = k >> 5, r = k & 31;
        float2 e = g_tw[((r * p) & 31) << 9];
        Wtab[k] = make_float2(e.x, -e.y);
    }
    __syncthreads();

    const float* xg = g_xt + (size_t)sig * NFFT;

    // ---- phase 1: stage A + N-twiddle -> Bq[q][r] in smem.
    // 2 passes of 16 q each: Wv read once per (p, pass) -> 64 LDS/warp total.
    int q0 = w * 32;
    float2 e0 = g_tw[(lane * q0) & (NFFT - 1)];
    float tc = e0.x, ts = -e0.y;            // e^{-2pi i lane q0 / N}
    float2 ed = g_tw[lane];
    float dc = ed.x, ds = -ed.y;            // step e^{-2pi i lane / N}

    for (int pp = 0; pp < 2; pp++) {
        int qb = q0 + pp * 16;
        float ar[16], ai[16];
#pragma unroll
        for (int k = 0; k < 16; k++) { ar[k] = 0.f; ai[k] = 0.f; }
#pragma unroll
        for (int p = 0; p < 32; p++) {
            float2 Wv = Wtab[(p << 5) + lane];            // 1 LDS.64 per p
#pragma unroll
            for (int t = 0; t < 4; t++) {
                float4 xv = *(const float4*)(xg + qb + 4 * t + (p << 9)); // broadcast
                ar[4*t+0] += xv.x * Wv.x; ai[4*t+0] += xv.x * Wv.y;
                ar[4*t+1] += xv.y * Wv.x; ai[4*t+1] += xv.y * Wv.y;
                ar[4*t+2] += xv.z * Wv.x; ai[4*t+2] += xv.z * Wv.y;
                ar[4*t+3] += xv.w * Wv.x; ai[4*t+3] += xv.w * Wv.y;
            }
        }
#pragma unroll
        for (int k = 0; k < 16; k++) {
            Bq[(qb + k) * 33 + lane] =
                make_float2(ar[k] * tc - ai[k] * ts, ar[k] * ts + ai[k] * tc);
            float ntc = tc * dc - ts * ds, nts = tc * ds + ts * dc;
            tc = ntc; ts = nts;
        }
    }
    __syncthreads();

    // ---- phase 2: 16-pt FFT over d (q = c + 32d), in place, per (c, r=lane)
    for (int tt = 0; tt < 2; tt++) {
        int c = w + tt * 16;
        float vr[16], vi[16];
#pragma unroll
        for (int d = 0; d < 16; d++) {
            float2 bv = Bq[(c + (d << 5)) * 33 + lane];
            vr[d] = bv.x; vi[d] = bv.y;
        }
        fft16<-1>(vr, vi);
#pragma unroll
        for (int j = 0; j < 16; j++)
            Bq[(c + (j << 5)) * 33 + lane] = make_float2(vr[j], vi[j]);
    }
    __syncthreads();

    // ---- phase 3: combine over c. warp w -> j = w, lane = r.
    {
        int j = w;
        float xr = 0.f, xi = 0.f;
#pragma unroll 8
        for (int c = 0; c < 32; c++) {
            float2 bv = Bq[(c + (j << 5)) * 33 + lane];
            float2 wv = w512[(j * c) & 511];               // broadcast
            xr += bv.x * wv.x - bv.y * wv.y;
            xi += bv.x * wv.y + bv.y * wv.x;
        }
        g_Xf[((size_t)b * MODES + lane + (j << 5)) * 32 + ci] = make_float2(xr, xi);
    }
}

// ------------------------------ channel mix --------------------------------
__global__ void k_einsum() {
    __shared__ float2 Xs[1024];   // [b][i]
    __shared__ float2 Wsm[1024];  // [i][o]
    int f = blockIdx.x, tid = threadIdx.x;
    for (int k = tid; k < 1024; k += 256) {
        Wsm[k] = g_Wt[f * 1024 + k];
        int bb = k >> 5, ii = k & 31;
        Xs[k] = g_Xf[((size_t)bb * MODES + f) * 32 + ii];
    }
    __syncthreads();
    int o = tid & 31, bg = tid >> 5;
    for (int bb = bg; bb < 32; bb += 8) {
        float yr = 0.f, yi = 0.f;
#pragma unroll
        for (int ii = 0; ii < 32; ii++) {
            float2 xv = Xs[bb * 32 + ii];
            float2 wv = Wsm[ii * 32 + o];
            yr += xv.x * wv.x - xv.y * wv.y;
            yi += xv.x * wv.y + xv.y * wv.x;
        }
        g_Y1[((size_t)bb * MODES + f) * 32 + o] = make_float2(yr, yi);
    }
}

// ----------------------------- frequency conv ------------------------------
__global__ void k_conv(const float* __restrict__ kre, const float* __restrict__ kim) {
    extern __shared__ float cs[];
    float2* Ys  = (float2*)cs;            // 68*32
    float*  krs = cs + 68 * 32 * 2;       // 5120
    float*  kis = krs + 5120;             // 5120
    int tx = threadIdx.x, ty = threadIdx.y;
    int tid = ty * 32 + tx;
    int b = blockIdx.y, f0 = blockIdx.x * 64;
    int nrows = min(68, 512 - f0);
    for (int k = tid; k < nrows * 32; k += 256)
        Ys[k] = g_Y1[((size_t)b * MODES + f0) * 32 + k];
    for (int k = tid; k < 5120; k += 256) { krs[k] = kre[k]; kis[k] = kim[k]; }
    __syncthreads();
    for (int c8 = 0; c8 < 8; c8++) {
        int fl = ty * 8 + c8;
        int f = f0 + fl;
        float gr = 0.f, gi = 0.f;
        if (f < FCONV) {
#pragma unroll
            for (int w5 = 0; w5 < 5; w5++)
#pragma unroll
                for (int c = 0; c < 32; c++) {
                    float2 yv = Ys[(fl + w5) * 32 + c];
                    gr += yv.x * krs[(w5 * 32 + c) * 32 + tx];
                    gi += yv.y * kis[(w5 * 32 + c) * 32 + tx];
                }
            float sc = (f == 0) ? (1.0f / NFFT) : (2.0f / NFFT);
            gr *= sc; gi *= sc;
        }
        g_G[((size_t)b * 32 + tx) * MODES + f] = make_float2(gr, gi);
    }
}

// ------------------------------ inverse DFT --------------------------------
// One block per signal. 512 threads, 1 CTA/SM.
__global__ __launch_bounds__(512, 1) void k_inv() {
    extern __shared__ float smem[];
    float*  Dre   = smem;                        // [512][33]
    float*  Dim   = Dre + 512 * 33;              // [512][33]
    float2* Gs    = (float2*)(Dim + 512 * 33);   // [j][33] padded (528)
    float2* w512p = Gs + 528;                    // e^{+2pi i t/512}
    float2* cs32  = w512p + 512;                 // (kept for layout)

    int sig = blockIdx.x;
    int tid = threadIdx.x, lane = tid & 31, w = tid >> 5;

    w512p[tid] = g_tw[(tid << 5) & (NFFT - 1)];
    if (tid < 32) cs32[tid] = g_tw[tid << 9];
    {   // G -> smem [j][r] padded; f = tid: r = tid&31, j = tid>>5
        float2 gv = g_G[(size_t)sig * MODES + tid];
        Gs[(tid >> 5) * 33 + (tid & 31)] = gv;
    }
    __syncthreads();

    // ---- phase A: per task (c, r=lane): twiddle + 16-pt inverse FFT + N-twiddle
    for (int tt = 0; tt < 2; tt++) {
        int c = w + tt * 16;
        float vr[16], vi[16];
#pragma unroll
        for (int j = 0; j < 16; j++) {
            float2 gv = Gs[j * 33 + lane];
            float2 wv = w512p[(j * c) & 511];          // broadcast
            vr[j] = gv.x * wv.x - gv.y * wv.y;
            vi[j] = gv.x * wv.y + gv.y * wv.x;
        }
        fft16<+1>(vr, vi);                              // j -> d
        float2 t0 = g_tw[(lane * c) & (NFFT - 1)];      // e^{+2pi i r c/N}
        float2 st = w512p[lane];                        // e^{+2pi i r/512}
        float tc = t0.x, ts = t0.y;
#pragma unroll
        for (int d = 0; d < 16; d++) {
            int m = c + (d << 5);
            Dre[m * 33 + lane] = vr[d] * tc - vi[d] * ts;
            Dim[m * 33 + lane] = vr[d] * ts + vi[d] * tc;
            float ntc = tc * st.x - ts * st.y, nts = tc * st.y + ts * st.x;
            tc = ntc; ts = nts;
        }
    }
    __syncthreads();

    // ---- phase B: 32-pt synthesis via 2x fft16 (DIT split).
    // y[s] = Re( sum_r D[r] e^{+2pi i r s/32} ):
    //   E = fft16(+1) of D[even r], O = fft16(+1) of D[odd r];
    //   y[k] = Er[k] + Re(w32^k O[k]); y[k+16] = Er[k] - Re(w32^k O[k]).
    {
        const float W32R[16] = {
            1.f,                    0.98078528040323044913f, 0.92387953251128675613f,
            0.83146961230254523708f, 0.70710678118654752440f, 0.55557023301960222474f,
            0.38268343236508977173f, 0.19509032201612826785f, 0.f,
            -0.19509032201612826785f, -0.38268343236508977173f, -0.55557023301960222474f,
            -0.70710678118654752440f, -0.83146961230254523708f, -0.92387953251128675613f,
            -0.98078528040323044913f };
        const float W32I[16] = {
            0.f,                    0.19509032201612826785f, 0.38268343236508977173f,
            0.55557023301960222474f, 0.70710678118654752440f, 0.83146961230254523708f,
            0.92387953251128675613f, 0.98078528040323044913f, 1.f,
            0.98078528040323044913f, 0.92387953251128675613f, 0.83146961230254523708f,
            0.70710678118654752440f, 0.55557023301960222474f, 0.38268343236508977173f,
            0.19509032201612826785f };
        float er[16], ei[16], odr[16], odi[16];
#pragma unroll
        for (int d = 0; d < 16; d++) {
            er[d]  = Dre[tid * 33 + 2 * d];     ei[d]  = Dim[tid * 33 + 2 * d];
            odr[d] = Dre[tid * 33 + 2 * d + 1]; odi[d] = Dim[tid * 33 + 2 * d + 1];
        }
        fft16<+1>(er, ei);
        fft16<+1>(odr, odi);
        float* yo = g_yt + (size_t)sig * NFFT + tid;   // m = tid; coalesced per s
#pragma unroll
        for (int k = 0; k < 16; k++) {
            float t = W32R[k] * odr[k] - W32I[k] * odi[k];
            yo[(size_t)k << 9]        = er[k] + t;
            yo[(size_t)(k + 16) << 9] = er[k] - t;
        }
    }
}

// g_yt [B,C,N] -> out [B,N,C]
__global__ void k_tout(float* __restrict__ out) {
    __shared__ float t[32][33];
    int tx = threadIdx.x, ty = threadIdx.y;
    int n0 = blockIdx.x * 32, b = blockIdx.y;
#pragma unroll
    for (int k = 0; k < 4; k++) {
        int c = ty + k * 8;
        t[c][tx] = g_yt[((size_t)b * 32 + c) * NFFT + n0 + tx];
    }
    __syncthreads();
#pragma unroll
    for (int k = 0; k < 4; k++) {
        int row = ty + k * 8;
        out[((size_t)b * NFFT + n0 + row) * 32 + tx] = t[tx][row];
    }
}

extern "C" void kernel_launch(void* const* d_in, const int* in_sizes, int n_in,
                              void* d_out, int out_size) {
    const float* x  = (const float*)d_in[0];
    const float* wr = (const float*)d_in[1];
    const float* wi = (const float*)d_in[2];
    const float* kr = (const float*)d_in[3];
    const float* ki = (const float*)d_in[4];
    float* out = (float*)d_out;

    cudaFuncSetAttribute(k_fwd,  cudaFuncAttributeMaxDynamicSharedMemorySize, SMEM_FWD);
    cudaFuncSetAttribute(k_inv,  cudaFuncAttributeMaxDynamicSharedMemorySize, SMEM_INV);
    cudaFuncSetAttribute(k_conv, cudaFuncAttributeMaxDynamicSharedMemorySize, SMEM_CONV);

    k_init<<<64, 256>>>();
    k_tin<<<dim3(NFFT / 32, 32), dim3(32, 8)>>>(x);
    k_wt<<<dim3(16, 32), dim3(32, 8)>>>(wr, wi);
    k_fwd<<<1024, 512, SMEM_FWD>>>();
    k_einsum<<<512, 256>>>();
    k_conv<<<dim3(8, 32), dim3(32, 8), SMEM_CONV>>>(kr, ki);
    k_inv<<<1024, 512, SMEM_INV>>>();
    k_tout<<<dim3(NFFT / 32, 32), dim3(32, 8)>>>(out);
}

// round 13
// speedup vs baseline: 3.1151x; 1.3336x over previous
#include <cuda_runtime.h>
#include <math.h>

// SpectralConv1d_plus: B=32, N=16384, C_in=C_out=32, MODES=512, conv width 5.
// Pruned transform with internal FFTs:
//   N = 512*32; f = r + 32j (r<32, j<16), n = q + 512p, q = c + 32d (c<32, d<16).
// forward:  A[r][q] = sum_p x[q+512p] e^{-2pi i r p/32}
//             -> computed per-lane (lane = q) as a REAL-input 32-pt FFT:
//                z[t] = x[q+1024t] + i x[q+1024t+512]; Z = fft16(z); Hermitian untangle.
//           B[r][q] = A[r][q] e^{-2pi i r q/N}          (rotator over r)
//           inner[c][j] = sum_d B[c+32d] e^{-2pi i jd/16}   (16-pt FFT, regs)
//           X[r+32j] = sum_c inner[c][j] e^{-2pi i jc/512}
// inverse (transpose): 16-pt inv FFT + rotator + 32-pt DIT synthesis.
// All normalizations fold into (f==0 ? 1 : 2)/N applied in k_conv.
// R11 lesson: broadcast LDG.128 returns 512B (4 wf) -> phase-1 x broadcasts were
// ~3/4 of L1 traffic. This round: lane=q, coalesced LDG.32 loads, real-FFT
// stage A (Hermitian savings included), scalar Bre/Bim (all smem 1-wf).

#define NFFT   16384
#define MODES  512
#define FCONV  508

__device__ float2 g_tw[NFFT];                   // e^{+2pi i k/N}
__device__ float  g_xt[32 * 32 * NFFT];         // [b][c][n]
__device__ float2 g_Xf[32 * MODES * 32];        // [b][f][i]
__device__ float2 g_Wt[MODES * 32 * 32];        // [f][i][o]
__device__ float2 g_Y1[32 * MODES * 32];        // [b][f][o]
__device__ float2 g_G [32 * 32 * MODES];        // [b][o][f]
__device__ float  g_yt[32 * 32 * NFFT];         // [b][o][n]

#define SMEM_FWD  ((512 * 33 * 2 + 1024) * 4)                 // 139264 B
#define SMEM_INV  ((512 * 33 * 2 + 1056 + 1024 + 64) * 4)     // 143744 B
#define SMEM_CONV ((68 * 32 * 2 + 2 * 5120) * 4)              // 58368 B

// ---------------- 16-point complex FFT, fully in registers -----------------
// Computes V[j] = sum_d v[d] e^{SGN*2pi i jd/16}, natural order in/out.
template<int SGN>
__device__ __forceinline__ void fft16(float vr[16], float vi[16]) {
#define SWP(a,b) { float t_=vr[a]; vr[a]=vr[b]; vr[b]=t_; \
                   t_=vi[a]; vi[a]=vi[b]; vi[b]=t_; }
    SWP(1,8) SWP(2,4) SWP(3,12) SWP(5,10) SWP(7,14) SWP(11,13)
#undef SWP
#define BFLY(i0,i1,wr,wi) { \
    const float wr_ = (wr), wi_ = (float)SGN * (wi); \
    float tr_ = wr_*vr[i1] - wi_*vi[i1]; \
    float ti_ = wr_*vi[i1] + wi_*vr[i1]; \
    vr[i1] = vr[i0] - tr_; vi[i1] = vi[i0] - ti_; \
    vr[i0] += tr_;         vi[i0] += ti_; }
    // len=2
    BFLY(0,1,1.f,0.f)  BFLY(2,3,1.f,0.f)  BFLY(4,5,1.f,0.f)  BFLY(6,7,1.f,0.f)
    BFLY(8,9,1.f,0.f)  BFLY(10,11,1.f,0.f) BFLY(12,13,1.f,0.f) BFLY(14,15,1.f,0.f)
    // len=4: w = 1, (0,SGN)
    BFLY(0,2,1.f,0.f)  BFLY(1,3,0.f,1.f)
    BFLY(4,6,1.f,0.f)  BFLY(5,7,0.f,1.f)
    BFLY(8,10,1.f,0.f) BFLY(9,11,0.f,1.f)
    BFLY(12,14,1.f,0.f) BFLY(13,15,0.f,1.f)
    // len=8: w = e^{SGN 2pi i k/8}, k=0..3
    {
        const float C8 = 0.70710678118654752f;
        BFLY(0,4,1.f,0.f)  BFLY(1,5,C8,C8)  BFLY(2,6,0.f,1.f)  BFLY(3,7,-C8,C8)
        BFLY(8,12,1.f,0.f) BFLY(9,13,C8,C8) BFLY(10,14,0.f,1.f) BFLY(11,15,-C8,C8)
    }
    // len=16: w = e^{SGN 2pi i k/16}, k=0..7
    {
        const float C8 = 0.70710678118654752f;
        const float CA = 0.92387953251128674f, SA = 0.38268343236508977f;
        BFLY(0,8,1.f,0.f)   BFLY(1,9,CA,SA)    BFLY(2,10,C8,C8)  BFLY(3,11,SA,CA)
        BFLY(4,12,0.f,1.f)  BFLY(5,13,-SA,CA)  BFLY(6,14,-C8,C8) BFLY(7,15,-CA,SA)
    }
#undef BFLY
}

// --------------------------------- init -----------------------------------
__global__ void k_init() {
    int k = blockIdx.x * blockDim.x + threadIdx.x;   // 64*256 = 16384
    float s, c;
    sincospif((float)k / 8192.0f, &s, &c);           // angle = 2*pi*k/N
    g_tw[k] = make_float2(c, s);
}

// x [B,N,C] -> g_xt [B,C,N]
__global__ void k_tin(const float* __restrict__ x) {
    __shared__ float t[32][33];
    int tx = threadIdx.x, ty = threadIdx.y;
    int n0 = blockIdx.x * 32, b = blockIdx.y;
#pragma unroll
    for (int k = 0; k < 4; k++) {
        int row = ty + k * 8;
        t[row][tx] = x[((size_t)b * NFFT + n0 + row) * 32 + tx];
    }
    __syncthreads();
#pragma unroll
    for (int k = 0; k < 4; k++) {
        int c = ty + k * 8;
        g_xt[((size_t)b * 32 + c) * NFFT + n0 + tx] = t[tx][c];
    }
}

// w_real/w_imag [i][o][f] -> g_Wt[f][i*32+o] float2
__global__ void k_wt(const float* __restrict__ wr, const float* __restrict__ wi) {
    __shared__ float tr[32][33], ti[32][33];
    int tx = threadIdx.x, ty = threadIdx.y;
    int f0 = blockIdx.x * 32, io0 = blockIdx.y * 32;
#pragma unroll
    for (int k = 0; k < 4; k++) {
        int row = ty + k * 8;
        tr[row][tx] = wr[(io0 + row) * MODES + f0 + tx];
        ti[row][tx] = wi[(io0 + row) * MODES + f0 + tx];
    }
    __syncthreads();
#pragma unroll
    for (int k = 0; k < 4; k++) {
        int fr = ty + k * 8;
        g_Wt[(f0 + fr) * 1024 + io0 + tx] = make_float2(tr[tx][fr], ti[tx][fr]);
    }
}

// ------------------------------ forward DFT --------------------------------
// One block per signal (b*32+i). 512 threads / 16 warps, 1 CTA/SM.
__global__ __launch_bounds__(512, 1) void k_fwd() {
    extern __shared__ float smem[];
    float*  Bre  = smem;                   // [q][r] padded: 512*33  (67.6 KB)
    float*  Bim  = Bre + 512 * 33;         // [q][r] padded: 512*33  (67.6 KB)
    float2* w512 = (float2*)(Bim + 512 * 33);  // e^{-2pi i t/512}   (4 KB)

    int sig = blockIdx.x, b = sig >> 5, ci = sig & 31;
    int tid = threadIdx.x, lane = tid & 31, w = tid >> 5;

    {
        float2 e = g_tw[(tid << 5) & (NFFT - 1)];
        w512[tid] = make_float2(e.x, -e.y);
    }
    __syncthreads();

    const float* xg = g_xt + (size_t)sig * NFFT;

    // ---- phase 1 (lane = q): real-input 32-pt FFT over p + N-twiddle -> Bre/Bim
    {
        const float W32R[16] = {
            1.f,                    0.98078528040323044913f, 0.92387953251128675613f,
            0.83146961230254523708f, 0.70710678118654752440f, 0.55557023301960222474f,
            0.38268343236508977173f, 0.19509032201612826785f, 0.f,
            -0.19509032201612826785f, -0.38268343236508977173f, -0.55557023301960222474f,
            -0.70710678118654752440f, -0.83146961230254523708f, -0.92387953251128675613f,
            -0.98078528040323044913f };
        const float W32I[16] = {
            0.f,                    0.19509032201612826785f, 0.38268343236508977173f,
            0.55557023301960222474f, 0.70710678118654752440f, 0.83146961230254523708f,
            0.92387953251128675613f, 0.98078528040323044913f, 1.f,
            0.98078528040323044913f, 0.92387953251128675613f, 0.83146961230254523708f,
            0.70710678118654752440f, 0.55557023301960222474f, 0.38268343236508977173f,
            0.19509032201612826785f };
        int q = (w << 5) + lane;
        const float* xq = xg + q;
        float zr[16], zi[16];
#pragma unroll
        for (int t = 0; t < 16; t++) {            // coalesced LDG.32 loads
            zr[t] = xq[t << 10];                  // x[q + 512*(2t)]
            zi[t] = xq[(t << 10) + 512];          // x[q + 512*(2t+1)]
        }
        fft16<-1>(zr, zi);                        // Z[k] = sum_t z e^{-2pi i kt/16}
        // Hermitian untangle: X[k] = Ze[k] + e^{-2pi i k/32} Zo[k], k=0..16
        float Xr[17], Xi[17];
#pragma unroll
        for (int k = 0; k < 16; k++) {
            int m = (16 - k) & 15;
            float Zer = 0.5f * (zr[k] + zr[m]);
            float Zei = 0.5f * (zi[k] - zi[m]);
            float Zor = 0.5f * (zi[k] + zi[m]);
            float Zoi = -0.5f * (zr[k] - zr[m]);
            Xr[k] = Zer + W32R[k] * Zor + W32I[k] * Zoi;
            Xi[k] = Zei + W32R[k] * Zoi - W32I[k] * Zor;
        }
        Xr[16] = zr[0] - zi[0];
        Xi[16] = 0.f;
        // B[r][q] = A[r] e^{-2pi i r q/N}; rotator over r, A[r>16] = conj(A[32-r])
        float2 ed = g_tw[q];
        float dc = ed.x, ds = -ed.y;              // step e^{-2pi i q/N}
        float tc = 1.f, ts = 0.f;
        int q33 = q * 33;
#pragma unroll
        for (int r = 0; r < 32; r++) {
            float Ar = (r <= 16) ? Xr[r] : Xr[32 - r];
            float Ai = (r <= 16) ? Xi[r] : -Xi[32 - r];
            Bre[q33 + r] = Ar * tc - Ai * ts;     // stride-33: conflict-free
            Bim[q33 + r] = Ar * ts + Ai * tc;
            float ntc = tc * dc - ts * ds, nts = tc * ds + ts * dc;
            tc = ntc; ts = nts;
        }
    }
    __syncthreads();

    // ---- phase 2: 16-pt FFT over d (q = c + 32d), in place, per (c, r=lane)
    for (int tt = 0; tt < 2; tt++) {
        int c = w + tt * 16;
        float vr[16], vi[16];
#pragma unroll
        for (int d = 0; d < 16; d++) {
            int idx = (c + (d << 5)) * 33 + lane;
            vr[d] = Bre[idx]; vi[d] = Bim[idx];
        }
        fft16<-1>(vr, vi);
#pragma unroll
        for (int j = 0; j < 16; j++) {
            int idx = (c + (j << 5)) * 33 + lane;
            Bre[idx] = vr[j]; Bim[idx] = vi[j];
        }
    }
    __syncthreads();

    // ---- phase 3: combine over c. warp w -> j = w, lane = r.
    {
        int j = w;
        float xr = 0.f, xi = 0.f;
#pragma unroll 8
        for (int c = 0; c < 32; c++) {
            int idx = (c + (j << 5)) * 33 + lane;
            float br = Bre[idx], bi = Bim[idx];
            float2 wv = w512[(j * c) & 511];               // broadcast
            xr += br * wv.x - bi * wv.y;
            xi += br * wv.y + bi * wv.x;
        }
        g_Xf[((size_t)b * MODES + lane + (j << 5)) * 32 + ci] = make_float2(xr, xi);
    }
}

// ------------------------------ channel mix --------------------------------
__global__ void k_einsum() {
    __shared__ float2 Xs[1024];   // [b][i]
    __shared__ float2 Wsm[1024];  // [i][o]
    int f = blockIdx.x, tid = threadIdx.x;
    for (int k = tid; k < 1024; k += 256) {
        Wsm[k] = g_Wt[f * 1024 + k];
        int bb = k >> 5, ii = k & 31;
        Xs[k] = g_Xf[((size_t)bb * MODES + f) * 32 + ii];
    }
    __syncthreads();
    int o = tid & 31, bg = tid >> 5;
    for (int bb = bg; bb < 32; bb += 8) {
        float yr = 0.f, yi = 0.f;
#pragma unroll
        for (int ii = 0; ii < 32; ii++) {
            float2 xv = Xs[bb * 32 + ii];
            float2 wv = Wsm[ii * 32 + o];
            yr += xv.x * wv.x - xv.y * wv.y;
            yi += xv.x * wv.y + xv.y * wv.x;
        }
        g_Y1[((size_t)bb * MODES + f) * 32 + o] = make_float2(yr, yi);
    }
}

// ----------------------------- frequency conv ------------------------------
__global__ void k_conv(const float* __restrict__ kre, const float* __restrict__ kim) {
    extern __shared__ float cs[];
    float2* Ys  = (float2*)cs;            // 68*32
    float*  krs = cs + 68 * 32 * 2;       // 5120
    float*  kis = krs + 5120;             // 5120
    int tx = threadIdx.x, ty = threadIdx.y;
    int tid = ty * 32 + tx;
    int b = blockIdx.y, f0 = blockIdx.x * 64;
    int nrows = min(68, 512 - f0);
    for (int k = tid; k < nrows * 32; k += 256)
        Ys[k] = g_Y1[((size_t)b * MODES + f0) * 32 + k];
    for (int k = tid; k < 5120; k += 256) { krs[k] = kre[k]; kis[k] = kim[k]; }
    __syncthreads();
    for (int c8 = 0; c8 < 8; c8++) {
        int fl = ty * 8 + c8;
        int f = f0 + fl;
        float gr = 0.f, gi = 0.f;
        if (f < FCONV) {
#pragma unroll
            for (int w5 = 0; w5 < 5; w5++)
#pragma unroll
                for (int c = 0; c < 32; c++) {
                    float2 yv = Ys[(fl + w5) * 32 + c];
                    gr += yv.x * krs[(w5 * 32 + c) * 32 + tx];
                    gi += yv.y * kis[(w5 * 32 + c) * 32 + tx];
                }
            float sc = (f == 0) ? (1.0f / NFFT) : (2.0f / NFFT);
            gr *= sc; gi *= sc;
        }
        g_G[((size_t)b * 32 + tx) * MODES + f] = make_float2(gr, gi);
    }
}

// ------------------------------ inverse DFT --------------------------------
// One block per signal. 512 threads, 1 CTA/SM.
__global__ __launch_bounds__(512, 1) void k_inv() {
    extern __shared__ float smem[];
    float*  Dre   = smem;                        // [512][33]
    float*  Dim   = Dre + 512 * 33;              // [512][33]
    float2* Gs    = (float2*)(Dim + 512 * 33);   // [j][33] padded (528)
    float2* w512p = Gs + 528;                    // e^{+2pi i t/512}
    float2* cs32  = w512p + 512;                 // (kept for layout)

    int sig = blockIdx.x;
    int tid = threadIdx.x, lane = tid & 31, w = tid >> 5;

    w512p[tid] = g_tw[(tid << 5) & (NFFT - 1)];
    if (tid < 32) cs32[tid] = g_tw[tid << 9];
    {   // G -> smem [j][r] padded; f = tid: r = tid&31, j = tid>>5
        float2 gv = g_G[(size_t)sig * MODES + tid];
        Gs[(tid >> 5) * 33 + (tid & 31)] = gv;
    }
    __syncthreads();

    // ---- phase A: per task (c, r=lane): twiddle + 16-pt inverse FFT + N-twiddle
    for (int tt = 0; tt < 2; tt++) {
        int c = w + tt * 16;
        float vr[16], vi[16];
#pragma unroll
        for (int j = 0; j < 16; j++) {
            float2 gv = Gs[j * 33 + lane];
            float2 wv = w512p[(j * c) & 511];          // broadcast
            vr[j] = gv.x * wv.x - gv.y * wv.y;
            vi[j] = gv.x * wv.y + gv.y * wv.x;
        }
        fft16<+1>(vr, vi);                              // j -> d
        float2 t0 = g_tw[(lane * c) & (NFFT - 1)];      // e^{+2pi i r c/N}
        float2 st = w512p[lane];                        // e^{+2pi i r/512}
        float tc = t0.x, ts = t0.y;
#pragma unroll
        for (int d = 0; d < 16; d++) {
            int m = c + (d << 5);
            Dre[m * 33 + lane] = vr[d] * tc - vi[d] * ts;
            Dim[m * 33 + lane] = vr[d] * ts + vi[d] * tc;
            float ntc = tc * st.x - ts * st.y, nts = tc * st.y + ts * st.x;
            tc = ntc; ts = nts;
        }
    }
    __syncthreads();

    // ---- phase B: 32-pt synthesis via 2x fft16 (DIT split).
    // y[s] = Re( sum_r D[r] e^{+2pi i r s/32} ):
    //   E = fft16(+1) of D[even r], O = fft16(+1) of D[odd r];
    //   y[k] = Er[k] + Re(w32^k O[k]); y[k+16] = Er[k] - Re(w32^k O[k]).
    {
        const float W32R[16] = {
            1.f,                    0.98078528040323044913f, 0.92387953251128675613f,
            0.83146961230254523708f, 0.70710678118654752440f, 0.55557023301960222474f,
            0.38268343236508977173f, 0.19509032201612826785f, 0.f,
            -0.19509032201612826785f, -0.38268343236508977173f, -0.55557023301960222474f,
            -0.70710678118654752440f, -0.83146961230254523708f, -0.92387953251128675613f,
            -0.98078528040323044913f };
        const float W32I[16] = {
            0.f,                    0.19509032201612826785f, 0.38268343236508977173f,
            0.55557023301960222474f, 0.70710678118654752440f, 0.83146961230254523708f,
            0.92387953251128675613f, 0.98078528040323044913f, 1.f,
            0.98078528040323044913f, 0.92387953251128675613f, 0.83146961230254523708f,
            0.70710678118654752440f, 0.55557023301960222474f, 0.38268343236508977173f,
            0.19509032201612826785f };
        float er[16], ei[16], odr[16], odi[16];
#pragma unroll
        for (int d = 0; d < 16; d++) {
            er[d]  = Dre[tid * 33 + 2 * d];     ei[d]  = Dim[tid * 33 + 2 * d];
            odr[d] = Dre[tid * 33 + 2 * d + 1]; odi[d] = Dim[tid * 33 + 2 * d + 1];
        }
        fft16<+1>(er, ei);
        fft16<+1>(odr, odi);
        float* yo = g_yt + (size_t)sig * NFFT + tid;   // m = tid; coalesced per s
#pragma unroll
        for (int k = 0; k < 16; k++) {
            float t = W32R[k] * odr[k] - W32I[k] * odi[k];
            yo[(size_t)k << 9]        = er[k] + t;
            yo[(size_t)(k + 16) << 9] = er[k] - t;
        }
    }
}

// g_yt [B,C,N] -> out [B,N,C]
__global__ void k_tout(float* __restrict__ out) {
    __shared__ float t[32][33];
    int tx = threadIdx.x, ty = threadIdx.y;
    int n0 = blockIdx.x * 32, b = blockIdx.y;
#pragma unroll
    for (int k = 0; k < 4; k++) {
        int c = ty + k * 8;
        t[c][tx] = g_yt[((size_t)b * 32 + c) * NFFT + n0 + tx];
    }
    __syncthreads();
#pragma unroll
    for (int k = 0; k < 4; k++) {
        int row = ty + k * 8;
        out[((size_t)b * NFFT + n0 + row) * 32 + tx] = t[tx][row];
    }
}

extern "C" void kernel_launch(void* const* d_in, const int* in_sizes, int n_in,
                              void* d_out, int out_size) {
    const float* x  = (const float*)d_in[0];
    const float* wr = (const float*)d_in[1];
    const float* wi = (const float*)d_in[2];
    const float* kr = (const float*)d_in[3];
    const float* ki = (const float*)d_in[4];
    float* out = (float*)d_out;

    cudaFuncSetAttribute(k_fwd,  cudaFuncAttributeMaxDynamicSharedMemorySize, SMEM_FWD);
    cudaFuncSetAttribute(k_inv,  cudaFuncAttributeMaxDynamicSharedMemorySize, SMEM_INV);
    cudaFuncSetAttribute(k_conv, cudaFuncAttributeMaxDynamicSharedMemorySize, SMEM_CONV);

    k_init<<<64, 256>>>();
    k_tin<<<dim3(NFFT / 32, 32), dim3(32, 8)>>>(x);
    k_wt<<<dim3(16, 32), dim3(32, 8)>>>(wr, wi);
    k_fwd<<<1024, 512, SMEM_FWD>>>();
    k_einsum<<<512, 256>>>();
    k_conv<<<dim3(8, 32), dim3(32, 8), SMEM_CONV>>>(kr, ki);
    k_inv<<<1024, 512, SMEM_INV>>>();
    k_tout<<<dim3(NFFT / 32, 32), dim3(32, 8)>>>(out);
}